// round 10
// baseline (speedup 1.0000x reference)
#include <cuda_runtime.h>
#include <cuda_bf16.h>
#include <math.h>
#include <stdint.h>

// Problem constants
#define BB 128
#define NN 49
#define CC 2048
#define DD 512
#define EE 512
#define VV 10000
#define TT 20
#define XD1 1024       // x = [vg | we]
#define GDIM 2560      // 4D gates + D gate-linear
#define MT (BB * TT)   // 2560 batched rows

typedef __nv_bfloat16 bf16;

// ---------------- device scratch ----------------
__device__ __align__(16) bf16 g_imgb[BB * NN * CC];
__device__ __align__(16) bf16 g_meanb[BB * CC];
__device__ __align__(16) bf16 g_Wbhmb[1536 * CC];
__device__ __align__(16) bf16 g_Wab[DD * CC];
__device__ __align__(16) bf16 g_Wvb[NN * DD];
__device__ __align__(16) bf16 g_Wgb[NN * DD];
__device__ __align__(16) bf16 g_Wsmb[NN * DD];
__device__ __align__(16) bf16 g_Vfb[BB * NN * DD];
__device__ __align__(16) bf16 g_xallb[MT * XD1];
__device__ __align__(16) bf16 g_Wxcatb[GDIM * XD1];   // gate-interleaved rows
__device__ __align__(16) bf16 g_Whci[GDIM * DD];      // gate-interleaved rows
__device__ __align__(16) bf16 g_WHb[DD * DD];
__device__ __align__(16) bf16 g_Wcb[DD * DD];
__device__ __align__(16) bf16 g_Wfcb[DD * DD];
__device__ __align__(16) bf16 g_Wpb[VV * DD];
__device__ __align__(16) bf16 g_hall[(TT + 1) * BB * DD];
__device__ __align__(16) bf16 g_uall[MT * DD];
__device__ __align__(16) bf16 g_Hallb[MT * DD];
__device__ __align__(16) bf16 g_sallb[MT * DD];
__device__ __align__(16) bf16 g_t1all[MT * DD];
__device__ __align__(16) bf16 g_o512all[MT * DD];
// fp32
__device__ __align__(16) float g_vghm[BB * 1536];
__device__ __align__(16) float g_zbase[BB * NN * NN];
__device__ __align__(16) float g_bbhm[1536];
__device__ __align__(16) float g_bcat[GDIM];          // gate-interleaved
__device__ __align__(16) float g_xpre[(size_t)MT * GDIM];  // gate-interleaved cols
__device__ __align__(16) float g_m[2][BB * DD];
__device__ __align__(16) float g_gHall[MT * NN];
__device__ __align__(16) float g_sWsall[MT * NN];

__device__ __forceinline__ float sigf(float x) { return 1.0f / (1.0f + expf(-x)); }

__device__ __forceinline__ uint4 ldsm4(uint32_t addr) {
    uint4 r;
    asm volatile("ldmatrix.sync.aligned.m8n8.x4.shared.b16 {%0,%1,%2,%3}, [%4];"
                 : "=r"(r.x), "=r"(r.y), "=r"(r.z), "=r"(r.w) : "r"(addr));
    return r;
}

__device__ __forceinline__ void mma16(float* c, const uint4 a, uint32_t b0, uint32_t b1) {
    asm volatile("mma.sync.aligned.m16n8k16.row.col.f32.bf16.bf16.f32 "
        "{%0,%1,%2,%3}, {%4,%5,%6,%7}, {%8,%9}, {%0,%1,%2,%3};"
        : "+f"(c[0]), "+f"(c[1]), "+f"(c[2]), "+f"(c[3])
        : "r"(a.x), "r"(a.y), "r"(a.z), "r"(a.w), "r"(b0), "r"(b1));
}

// ============ 128x64 bf16 GEMM body (256 threads) — small-N GEMMs ============
template <int ACT, int OUT, int REMAP>
__device__ __forceinline__ void gemm2_body(
    const bf16* __restrict__ A, int lda,
    const bf16* __restrict__ W, int ldw,
    const float* __restrict__ bias,
    float* __restrict__ C, bf16* __restrict__ Cb,
    long long ldc, int N, int K)
{
    __shared__ __align__(16) bf16 sA[128 * 40];
    __shared__ __align__(16) bf16 sB[64 * 40];

    const int tid = threadIdx.x;
    const int lane = tid & 31, w = tid >> 5;
    const int wm = (w >> 1) * 32, wn = (w & 1) * 32;
    const int m0 = blockIdx.y * 128, n0 = blockIdx.x * 64;
    const int g = lane >> 2, q = lane & 3;
    const int arow = tid >> 1, ac0 = (tid & 1) * 2;
    const int brow = tid >> 2, bc0 = tid & 3;
    const uint4 z4 = make_uint4(0, 0, 0, 0);

    const uint32_t baseA = (uint32_t)__cvta_generic_to_shared(sA);
    const uint32_t baseB = (uint32_t)__cvta_generic_to_shared(sB);
    const int rA = wm + (lane & 7) + ((lane >> 3) & 1) * 8;
    const uint32_t offA0 = baseA + (uint32_t)(rA * 40 + (lane >> 4) * 8) * 2;
    const int rB = wn + (lane & 7);
    const uint32_t offB0 = baseB + (uint32_t)(rB * 40 + (lane >> 3) * 8) * 2;

    float acc[2][4][4];
#pragma unroll
    for (int i = 0; i < 2; i++)
#pragma unroll
        for (int j = 0; j < 4; j++)
#pragma unroll
            for (int u = 0; u < 4; u++) acc[i][j][u] = 0.f;

    uint4 pa[2], pb;
    auto load_regs = [&](int k0) {
#pragma unroll
        for (int e = 0; e < 2; e++)
            pa[e] = *reinterpret_cast<const uint4*>(A + (size_t)(m0 + arow) * lda + k0 + (ac0 + e) * 8);
        pb = (n0 + brow < N)
            ? *reinterpret_cast<const uint4*>(W + (size_t)(n0 + brow) * ldw + k0 + bc0 * 8)
            : z4;
    };
    auto store_smem = [&]() {
#pragma unroll
        for (int e = 0; e < 2; e++)
            *reinterpret_cast<uint4*>(&sA[arow * 40 + (ac0 + e) * 8]) = pa[e];
        *reinterpret_cast<uint4*>(&sB[brow * 40 + bc0 * 8]) = pb;
    };

    load_regs(0);
    store_smem();

    for (int k0 = 0; k0 < K; k0 += 32) {
        __syncthreads();
        const bool more = (k0 + 32) < K;
        if (more) load_regs(k0 + 32);

        uint4 bfr[4];
#pragma unroll
        for (int j = 0; j < 4; j++) bfr[j] = ldsm4(offB0 + j * 640);
#pragma unroll
        for (int kt = 0; kt < 2; kt++) {
            uint4 af0 = ldsm4(offA0 + kt * 32);
            uint4 af1 = ldsm4(offA0 + 1280 + kt * 32);
#pragma unroll
            for (int j = 0; j < 4; j++) {
                const uint32_t b0 = kt ? bfr[j].z : bfr[j].x;
                const uint32_t b1 = kt ? bfr[j].w : bfr[j].y;
                mma16(acc[0][j], af0, b0, b1);
                mma16(acc[1][j], af1, b0, b1);
            }
        }
        if (more) {
            __syncthreads();
            store_smem();
        }
    }

#pragma unroll
    for (int i = 0; i < 2; i++) {
        const int r0 = m0 + wm + i * 16 + g;
        const long long orow0 = REMAP ? (long long)((r0 & 127) * TT + (r0 >> 7)) : (long long)r0;
        const long long orow1 = REMAP ? (long long)(((r0 + 8) & 127) * TT + ((r0 + 8) >> 7)) : (long long)(r0 + 8);
#pragma unroll
        for (int j = 0; j < 4; j++) {
            const int col = n0 + wn + j * 8 + q * 2;
            float b0v = 0.f, b1v = 0.f;
            if (bias) {
                if (col < N)     b0v = bias[col];
                if (col + 1 < N) b1v = bias[col + 1];
            }
            float v00 = acc[i][j][0] + b0v, v01 = acc[i][j][1] + b1v;
            float v10 = acc[i][j][2] + b0v, v11 = acc[i][j][3] + b1v;
            if (ACT == 1) {
                v00 = fmaxf(v00, 0.f); v01 = fmaxf(v01, 0.f);
                v10 = fmaxf(v10, 0.f); v11 = fmaxf(v11, 0.f);
            } else if (ACT == 2) {
                v00 = tanhf(v00); v01 = tanhf(v01);
                v10 = tanhf(v10); v11 = tanhf(v11);
            }
            if (col < N) {
                if (OUT == 0) { C[orow0 * ldc + col] = v00; C[orow1 * ldc + col] = v10; }
                else { Cb[orow0 * ldc + col] = __float2bfloat16(v00);
                       Cb[orow1 * ldc + col] = __float2bfloat16(v10); }
            }
            if (col + 1 < N) {
                if (OUT == 0) { C[orow0 * ldc + col + 1] = v01; C[orow1 * ldc + col + 1] = v11; }
                else { Cb[orow0 * ldc + col + 1] = __float2bfloat16(v01);
                       Cb[orow1 * ldc + col + 1] = __float2bfloat16(v11); }
            }
        }
    }
}

template <int ACT, int OUT, int REMAP>
__global__ __launch_bounds__(256) void gemm2(
    const bf16* __restrict__ A, int lda,
    const bf16* __restrict__ W, int ldw,
    const float* __restrict__ bias,
    float* __restrict__ C, bf16* __restrict__ Cb, long long ldc, int N, int K)
{
    gemm2_body<ACT, OUT, REMAP>(A, lda, W, ldw, bias, C, Cb, ldc, N, K);
}

// ============ 128x128 bf16 GEMM body (256 threads, 8 warps 4x2) ============
template <int ACT, int OUT, int REMAP>
__device__ __forceinline__ void gemm3_body(
    const bf16* __restrict__ A, int lda,
    const bf16* __restrict__ W, int ldw,
    const float* __restrict__ bias,
    float* __restrict__ C, bf16* __restrict__ Cb,
    long long ldc, int N, int K)
{
    __shared__ __align__(16) bf16 sA[128 * 40];
    __shared__ __align__(16) bf16 sB[128 * 40];

    const int tid = threadIdx.x;
    const int lane = tid & 31, w = tid >> 5;
    const int wm = (w >> 1) * 32, wn = (w & 1) * 64;   // 4x2 warp grid, tile 32x64
    const int m0 = blockIdx.y * 128, n0 = blockIdx.x * 128;
    const int g = lane >> 2, q = lane & 3;
    const int arow = tid >> 1, ac0 = (tid & 1) * 2;    // 2 uint4 per thread per operand
    const uint4 z4 = make_uint4(0, 0, 0, 0);

    const uint32_t baseA = (uint32_t)__cvta_generic_to_shared(sA);
    const uint32_t baseB = (uint32_t)__cvta_generic_to_shared(sB);
    const int rA = wm + (lane & 7) + ((lane >> 3) & 1) * 8;
    const uint32_t offA0 = baseA + (uint32_t)(rA * 40 + (lane >> 4) * 8) * 2;
    const int rB = wn + (lane & 7);
    const uint32_t offB0 = baseB + (uint32_t)(rB * 40 + (lane >> 3) * 8) * 2;

    float acc[2][8][4];
#pragma unroll
    for (int i = 0; i < 2; i++)
#pragma unroll
        for (int j = 0; j < 8; j++)
#pragma unroll
            for (int u = 0; u < 4; u++) acc[i][j][u] = 0.f;

    uint4 pa[2], pb[2];
    auto load_regs = [&](int k0) {
#pragma unroll
        for (int e = 0; e < 2; e++) {
            pa[e] = *reinterpret_cast<const uint4*>(A + (size_t)(m0 + arow) * lda + k0 + (ac0 + e) * 8);
            pb[e] = (n0 + arow < N)
                ? *reinterpret_cast<const uint4*>(W + (size_t)(n0 + arow) * ldw + k0 + (ac0 + e) * 8)
                : z4;
        }
    };
    auto store_smem = [&]() {
#pragma unroll
        for (int e = 0; e < 2; e++) {
            *reinterpret_cast<uint4*>(&sA[arow * 40 + (ac0 + e) * 8]) = pa[e];
            *reinterpret_cast<uint4*>(&sB[arow * 40 + (ac0 + e) * 8]) = pb[e];
        }
    };

    load_regs(0);
    store_smem();

    for (int k0 = 0; k0 < K; k0 += 32) {
        __syncthreads();
        const bool more = (k0 + 32) < K;
        if (more) load_regs(k0 + 32);

        uint4 bfr[8];
#pragma unroll
        for (int j = 0; j < 8; j++) bfr[j] = ldsm4(offB0 + j * 640);
#pragma unroll
        for (int kt = 0; kt < 2; kt++) {
            uint4 af0 = ldsm4(offA0 + kt * 32);
            uint4 af1 = ldsm4(offA0 + 1280 + kt * 32);
#pragma unroll
            for (int j = 0; j < 8; j++) {
                const uint32_t b0 = kt ? bfr[j].z : bfr[j].x;
                const uint32_t b1 = kt ? bfr[j].w : bfr[j].y;
                mma16(acc[0][j], af0, b0, b1);
                mma16(acc[1][j], af1, b0, b1);
            }
        }
        if (more) {
            __syncthreads();
            store_smem();
        }
    }

#pragma unroll
    for (int i = 0; i < 2; i++) {
        const int r0 = m0 + wm + i * 16 + g;
        const long long orow0 = REMAP ? (long long)((r0 & 127) * TT + (r0 >> 7)) : (long long)r0;
        const long long orow1 = REMAP ? (long long)(((r0 + 8) & 127) * TT + ((r0 + 8) >> 7)) : (long long)(r0 + 8);
#pragma unroll
        for (int j = 0; j < 8; j++) {
            const int col = n0 + wn + j * 8 + q * 2;
            float b0v = 0.f, b1v = 0.f;
            if (bias) {
                if (col < N)     b0v = bias[col];
                if (col + 1 < N) b1v = bias[col + 1];
            }
            float v00 = acc[i][j][0] + b0v, v01 = acc[i][j][1] + b1v;
            float v10 = acc[i][j][2] + b0v, v11 = acc[i][j][3] + b1v;
            if (ACT == 1) {
                v00 = fmaxf(v00, 0.f); v01 = fmaxf(v01, 0.f);
                v10 = fmaxf(v10, 0.f); v11 = fmaxf(v11, 0.f);
            } else if (ACT == 2) {
                v00 = tanhf(v00); v01 = tanhf(v01);
                v10 = tanhf(v10); v11 = tanhf(v11);
            }
            if (col < N) {
                if (OUT == 0) { C[orow0 * ldc + col] = v00; C[orow1 * ldc + col] = v10; }
                else { Cb[orow0 * ldc + col] = __float2bfloat16(v00);
                       Cb[orow1 * ldc + col] = __float2bfloat16(v10); }
            }
            if (col + 1 < N) {
                if (OUT == 0) { C[orow0 * ldc + col + 1] = v01; C[orow1 * ldc + col + 1] = v11; }
                else { Cb[orow0 * ldc + col + 1] = __float2bfloat16(v01);
                       Cb[orow1 * ldc + col + 1] = __float2bfloat16(v11); }
            }
        }
    }
}

template <int ACT, int OUT, int REMAP>
__global__ __launch_bounds__(256) void gemm3(
    const bf16* __restrict__ A, int lda,
    const bf16* __restrict__ W, int ldw,
    const float* __restrict__ bias,
    float* __restrict__ C, bf16* __restrict__ Cb, long long ldc, int N, int K)
{
    gemm3_body<ACT, OUT, REMAP>(A, lda, W, ldw, bias, C, Cb, ldc, N, K);
}

__global__ __launch_bounds__(256) void hs_batched(const float* __restrict__ bc)
{
    if (blockIdx.z == 0)
        gemm3_body<1, 2, 0>(g_hall + BB * DD, DD, g_WHb, DD, nullptr, nullptr, g_Hallb, DD, DD, DD);
    else
        gemm3_body<1, 2, 0>(g_uall, DD, g_Wcb, DD, bc, nullptr, g_sallb, DD, DD, DD);
}

__global__ __launch_bounds__(256) void ghsw_batched()
{
    if (blockIdx.z == 0)
        gemm2_body<0, 0, 0>(g_Hallb, DD, g_Wgb, DD, nullptr, g_gHall, nullptr, NN, NN, DD);
    else
        gemm2_body<0, 0, 0>(g_sallb, DD, g_Wsmb, DD, nullptr, g_sWsall, nullptr, NN, NN, DD);
}

// ============ fused recurrence step: 64x320 GEMM + LSTM epilogue ============
// grid: (8 D-strips, 2 m-tiles), 256 threads. Gate-interleaved layout:
// strip col r = g*64 + dd holds gate g for unit d = D*64+dd.
__global__ __launch_bounds__(256) void step_fused(int t)
{
    const int D = blockIdx.x, mi = blockIdx.y;
    const int m0 = mi * 64;
    const int tid = threadIdx.x;
    const int lane = tid & 31, w = tid >> 5;
    const int wr = w >> 2, wc = w & 3;         // 2x4 warp grid
    const int wm = wr * 32, wn = wc * 80;      // warp tile 32x80
    const int g = lane >> 2, q = lane & 3;
    const int arow = tid >> 2, ac = tid & 3;

    __shared__ __align__(16) bf16 sA[64 * 40];
    __shared__ __align__(16) char ubuf[41088];   // max(320*40*2=25600, 32*321*4=41088)
    bf16* sB = reinterpret_cast<bf16*>(ubuf);
    float* stage = reinterpret_cast<float*>(ubuf);

    const bf16* A = g_hall + (size_t)t * BB * DD;
    const bf16* W = g_Whci + (size_t)D * 320 * DD;
    const float* Ci = g_xpre + (size_t)t * BB * GDIM + D * 320;

    const uint32_t baseA = (uint32_t)__cvta_generic_to_shared(sA);
    const uint32_t baseB = (uint32_t)__cvta_generic_to_shared(sB);
    const int rA = wm + (lane & 7) + ((lane >> 3) & 1) * 8;
    const uint32_t offA0 = baseA + (uint32_t)(rA * 40 + (lane >> 4) * 8) * 2;
    const int rB = wn + (lane & 7);
    const uint32_t offB0 = baseB + (uint32_t)(rB * 40 + (lane >> 3) * 8) * 2;

    float acc[2][10][4];
#pragma unroll
    for (int i = 0; i < 2; i++)
#pragma unroll
        for (int j = 0; j < 10; j++)
#pragma unroll
            for (int u = 0; u < 4; u++) acc[i][j][u] = 0.f;

    uint4 pa, pb[5];
    auto load_regs = [&](int k0) {
        pa = *reinterpret_cast<const uint4*>(A + (size_t)(m0 + arow) * DD + k0 + ac * 8);
#pragma unroll
        for (int e = 0; e < 5; e++)
            pb[e] = *reinterpret_cast<const uint4*>(W + (size_t)(arow + 64 * e) * DD + k0 + ac * 8);
    };
    auto store_smem = [&]() {
        *reinterpret_cast<uint4*>(&sA[arow * 40 + ac * 8]) = pa;
#pragma unroll
        for (int e = 0; e < 5; e++)
            *reinterpret_cast<uint4*>(&sB[(arow + 64 * e) * 40 + ac * 8]) = pb[e];
    };

    load_regs(0);
    store_smem();
    for (int k0 = 0; k0 < DD; k0 += 32) {
        __syncthreads();
        const bool more = (k0 + 32) < DD;
        if (more) load_regs(k0 + 32);
        uint4 bfr[10];
#pragma unroll
        for (int j = 0; j < 10; j++) bfr[j] = ldsm4(offB0 + j * 640);
#pragma unroll
        for (int kt = 0; kt < 2; kt++) {
            uint4 af0 = ldsm4(offA0 + kt * 32);
            uint4 af1 = ldsm4(offA0 + 1280 + kt * 32);
#pragma unroll
            for (int j = 0; j < 10; j++) {
                const uint32_t b0 = kt ? bfr[j].z : bfr[j].x;
                const uint32_t b1 = kt ? bfr[j].w : bfr[j].y;
                mma16(acc[0][j], af0, b0, b1);
                mma16(acc[1][j], af1, b0, b1);
            }
        }
        if (more) {
            __syncthreads();
            store_smem();
        }
    }
    __syncthreads();   // sB reads done; ubuf becomes stage

    const int cur = t & 1, nxt = cur ^ 1;
#pragma unroll
    for (int half = 0; half < 2; half++) {
        if (wr == half) {
#pragma unroll
            for (int i = 0; i < 2; i++) {
                const int lr0 = i * 16 + g;     // local row within half
#pragma unroll
                for (int j = 0; j < 10; j++) {
                    const int col = wn + j * 8 + q * 2;
                    stage[lr0 * 321 + col]           = acc[i][j][0];
                    stage[lr0 * 321 + col + 1]       = acc[i][j][1];
                    stage[(lr0 + 8) * 321 + col]     = acc[i][j][2];
                    stage[(lr0 + 8) * 321 + col + 1] = acc[i][j][3];
                }
            }
        }
        __syncthreads();
        // LSTM on 32 rows x 64 units
#pragma unroll
        for (int e = 0; e < 8; e++) {
            const int li = tid + e * 256;       // 0..2047
            const int lr = li >> 6, dd = li & 63;
            const int b = m0 + half * 32 + lr;
            const int d = D * 64 + dd;
            const int idx = b * DD + d;
            const float* ci = Ci + (size_t)b * GDIM;
            float gi = stage[lr * 321 + dd]        + ci[dd];
            float gf = stage[lr * 321 + 64 + dd]   + ci[64 + dd];
            float gg = stage[lr * 321 + 128 + dd]  + ci[128 + dd];
            float go = stage[lr * 321 + 192 + dd]  + ci[192 + dd];
            float gl = stage[lr * 321 + 256 + dd]  + ci[256 + dd];
            float m2 = sigf(gf) * g_m[cur][idx] + sigf(gi) * tanhf(gg);
            float tm2 = tanhf(m2);
            g_m[nxt][idx] = m2;
            g_hall[(size_t)(t + 1) * BB * DD + idx] = __float2bfloat16(sigf(go) * tm2);
            g_uall[(size_t)t * BB * DD + idx] = __float2bfloat16(sigf(gl) * tm2);
        }
        __syncthreads();
    }
}

// ---------------- conversion / setup kernels ----------------
__global__ void cvt_bf16_kernel(const float* __restrict__ in, bf16* __restrict__ out, int n4)
{
    int idx = blockIdx.x * blockDim.x + threadIdx.x;
    if (idx >= n4) return;
    float4 v = reinterpret_cast<const float4*>(in)[idx];
    reinterpret_cast<__nv_bfloat162*>(out)[idx * 2]     = __floats2bfloat162_rn(v.x, v.y);
    reinterpret_cast<__nv_bfloat162*>(out)[idx * 2 + 1] = __floats2bfloat162_rn(v.z, v.w);
}

__global__ void mean_kernel(const float* __restrict__ img)
{
    int idx = blockIdx.x * blockDim.x + threadIdx.x;
    if (idx >= BB * CC) return;
    int b = idx / CC, c = idx % CC;
    const float* p = img + (size_t)b * NN * CC + c;
    float s = 0.f;
#pragma unroll 7
    for (int n = 0; n < NN; n++) s += p[(size_t)n * CC];
    g_meanb[idx] = __float2bfloat16(s * (1.0f / NN));
}

__global__ void build_wbhm_kernel(const float* __restrict__ Wb, const float* __restrict__ Whi,
                                  const float* __restrict__ Wmi,
                                  const float* __restrict__ bb, const float* __restrict__ bhi,
                                  const float* __restrict__ bmi)
{
    int idx = blockIdx.x * blockDim.x + threadIdx.x;
    if (idx >= 1536 * CC) return;
    int r = idx / CC, c = idx % CC;
    float v;
    if (r < 512)       v = Wb[(size_t)r * CC + c];
    else if (r < 1024) v = Whi[(size_t)(r - 512) * CC + c];
    else               v = Wmi[(size_t)(r - 1024) * CC + c];
    g_Wbhmb[idx] = __float2bfloat16(v);
    if (c == 0) g_bbhm[r] = (r < 512) ? bb[r] : (r < 1024 ? bhi[r - 512] : bmi[r - 1024]);
}

// gate-interleaved: permuted row p -> D=p/320, rr=p%320, gate=rr/64, dd=rr%64
// orig row = gate*512 + D*64 + dd (gate<4 from Wih/Whh) or Wx/Wh2 row D*64+dd (gate 4)
__global__ void build_wxcat_kernel(const float* __restrict__ Wih, const float* __restrict__ Wx,
                                   const float* __restrict__ bih, const float* __restrict__ bhh)
{
    int idx = blockIdx.x * blockDim.x + threadIdx.x;
    if (idx >= GDIM * XD1) return;
    int p = idx / XD1, c = idx % XD1;
    int Dq = p / 320, rr = p % 320, gt = rr / 64, dd = rr % 64;
    float v;
    if (gt < 4) {
        int orig = gt * 512 + Dq * 64 + dd;
        v = Wih[(size_t)orig * XD1 + c];
        if (c == 0) g_bcat[p] = bih[orig] + bhh[orig];
    } else {
        int orig = Dq * 64 + dd;
        v = Wx[(size_t)orig * XD1 + c];
        if (c == 0) g_bcat[p] = 0.f;
    }
    g_Wxcatb[(size_t)p * XD1 + c] = __float2bfloat16(v);
}

__global__ void build_whci_kernel(const float* __restrict__ Whh, const float* __restrict__ Wh2)
{
    int idx = blockIdx.x * blockDim.x + threadIdx.x;
    if (idx >= GDIM * DD) return;
    int p = idx / DD, c = idx % DD;
    int Dq = p / 320, rr = p % 320, gt = rr / 64, dd = rr % 64;
    float v = (gt < 4) ? Whh[(size_t)(gt * 512 + Dq * 64 + dd) * DD + c]
                       : Wh2[(size_t)(Dq * 64 + dd) * DD + c];
    g_Whci[(size_t)p * DD + c] = __float2bfloat16(v);
}

__global__ void hm_init_kernel()
{
    int idx = blockIdx.x * blockDim.x + threadIdx.x;
    if (idx >= BB * DD) return;
    int b = idx >> 9, d = idx & 511;
    g_hall[idx] = __float2bfloat16(g_vghm[b * 1536 + 512 + d]);
    g_m[0][idx] = g_vghm[b * 1536 + 1024 + d];
}

__global__ void xall_init_kernel(const float* __restrict__ emb, const int* __restrict__ target)
{
    int idx = blockIdx.x * blockDim.x + threadIdx.x;
    if (idx >= MT * XD1) return;
    int j = idx % XD1;
    int tb = idx / XD1;
    int b = tb % BB;
    int t = tb / BB;
    float v;
    if (j < 512) v = g_vghm[b * 1536 + j];
    else if (t == 0) v = 0.f;
    else {
        int tok = target[b * TT + t - 1];
        v = emb[(size_t)tok * EE + (j - 512)];
    }
    g_xallb[((size_t)t * BB + b) * XD1 + j] = __float2bfloat16(v);
}

// batched attention
__global__ void attn_fused_kernel(const float* __restrict__ wh, float* __restrict__ attn_out)
{
    const int r = blockIdx.x;            // t*128 + b
    const int t = r >> 7, b = r & 127;
    __shared__ float gHs[49], sWss[49], zsh[50], wsh[49];
    int tid = threadIdx.x;  // 128

    if (tid < 49) {
        gHs[tid] = g_gHall[r * 49 + tid];
        sWss[tid] = g_sWsall[r * 49 + tid];
        wsh[tid] = wh[tid];
    }
    __syncthreads();

    if (tid < 49) {
        const float* zb = g_zbase + ((size_t)b * 49 + tid) * 49;
        float acc = 0.f;
#pragma unroll 7
        for (int k = 0; k < 49; k++) acc += tanhf(zb[k] + gHs[k]) * wsh[k];
        zsh[tid] = acc;
    } else if (tid == 49) {
        float acc = 0.f;
#pragma unroll 7
        for (int k = 0; k < 49; k++) acc += tanhf(sWss[k] + gHs[k]) * wsh[k];
        zsh[49] = acc;
    }
    __syncthreads();

    if (tid == 0) {
        float mx = -1e30f;
        for (int i = 0; i < 50; i++) mx = fmaxf(mx, zsh[i]);
        float sum = 0.f;
        for (int i = 0; i < 50; i++) { zsh[i] = expf(zsh[i] - mx); sum += zsh[i]; }
        float inv = 1.f / sum;
        for (int i = 0; i < 50; i++) zsh[i] *= inv;
    }
    __syncthreads();

    if (tid < 49) attn_out[((size_t)b * TT + t) * 49 + tid] = zsh[tid];

    const float a50 = zsh[49];
    const bf16* srow = g_sallb + (size_t)r * 512;
    const bf16* Hrow = g_Hallb + (size_t)r * 512;
#pragma unroll
    for (int e = 0; e < 4; e++) {
        int d = tid + e * 128;
        float acc = a50 * __bfloat162float(srow[d]);
#pragma unroll 7
        for (int n = 0; n < 49; n++)
            acc = fmaf(zsh[n], __bfloat162float(g_Vfb[((size_t)b * 49 + n) * 512 + d]), acc);
        g_t1all[(size_t)r * 512 + d] = __float2bfloat16(__bfloat162float(Hrow[d]) + acc);
    }
}

// online single-pass max+sum log-softmax, float4
__global__ void log_softmax_kernel(float* __restrict__ logits)
{
    const int row = blockIdx.x;
    float4* x4 = reinterpret_cast<float4*>(logits + (size_t)row * VV);
    const int tid = threadIdx.x;  // 256
    float mx = -1e30f, sm = 0.f;
    for (int i = tid; i < VV / 4; i += 256) {
        float4 v = x4[i];
        float m2 = fmaxf(fmaxf(v.x, v.y), fmaxf(v.z, v.w));
        if (m2 > mx) { sm *= expf(mx - m2); mx = m2; }
        sm += expf(v.x - mx) + expf(v.y - mx) + expf(v.z - mx) + expf(v.w - mx);
    }
    __shared__ float smx[256], ssm[256];
    smx[tid] = mx; ssm[tid] = sm;
    __syncthreads();
    for (int s = 128; s; s >>= 1) {
        if (tid < s) {
            float m2 = fmaxf(smx[tid], smx[tid + s]);
            ssm[tid] = ssm[tid] * expf(smx[tid] - m2) + ssm[tid + s] * expf(smx[tid + s] - m2);
            smx[tid] = m2;
        }
        __syncthreads();
    }
    const float lse = smx[0] + logf(ssm[0]);
    for (int i = tid; i < VV / 4; i += 256) {
        float4 v = x4[i];
        v.x -= lse; v.y -= lse; v.z -= lse; v.w -= lse;
        x4[i] = v;
    }
}

// ---------------- host ----------------
static inline dim3 t2grid(int M, int N) { return dim3((N + 63) / 64, M / 128); }
static inline dim3 t3grid(int M, int N) { return dim3((N + 127) / 128, M / 128); }

extern "C" void kernel_launch(void* const* d_in, const int* in_sizes, int n_in,
                              void* d_out, int out_size)
{
    const float* img    = (const float*)d_in[0];
    const int*   target = (const int*)d_in[1];
    const float* emb    = (const float*)d_in[2];
    const float* Wa  = (const float*)d_in[3];  const float* ba  = (const float*)d_in[4];
    const float* Wb  = (const float*)d_in[5];  const float* bb  = (const float*)d_in[6];
    const float* Whi = (const float*)d_in[7];  const float* bhi = (const float*)d_in[8];
    const float* Wmi = (const float*)d_in[9];  const float* bmi = (const float*)d_in[10];
    const float* Wih = (const float*)d_in[11]; const float* bih = (const float*)d_in[12];
    const float* Whh = (const float*)d_in[13]; const float* bhh = (const float*)d_in[14];
    const float* Wv  = (const float*)d_in[15];
    const float* Wg  = (const float*)d_in[16];
    const float* wh  = (const float*)d_in[17];
    const float* WH  = (const float*)d_in[18];
    const float* Wx  = (const float*)d_in[19];
    const float* Wh2 = (const float*)d_in[20];
    const float* Wsm = (const float*)d_in[21];
    const float* Wc  = (const float*)d_in[22]; const float* bc  = (const float*)d_in[23];
    const float* Wfc = (const float*)d_in[24]; const float* bfc = (const float*)d_in[25];
    const float* Wp  = (const float*)d_in[26]; const float* bp  = (const float*)d_in[27];

    float* out_logits = (float*)d_out;                               // [B,T,VOC]
    float* out_attn   = (float*)d_out + (size_t)BB * TT * VV;        // [B,T,N]

    bf16 *p_imgb, *p_meanb, *p_Wbhmb, *p_Wab, *p_Wvb, *p_Wgb, *p_Wsmb, *p_Vfb, *p_xallb;
    bf16 *p_Wxcatb, *p_WHb, *p_Wcb, *p_Wfcb, *p_Wpb, *p_hall, *p_t1all, *p_o512all;
    float *p_vghm, *p_zbase, *p_bbhm, *p_bcat, *p_xpre;
    cudaGetSymbolAddress((void**)&p_imgb,   g_imgb);
    cudaGetSymbolAddress((void**)&p_meanb,  g_meanb);
    cudaGetSymbolAddress((void**)&p_Wbhmb,  g_Wbhmb);
    cudaGetSymbolAddress((void**)&p_Wab,    g_Wab);
    cudaGetSymbolAddress((void**)&p_Wvb,    g_Wvb);
    cudaGetSymbolAddress((void**)&p_Wgb,    g_Wgb);
    cudaGetSymbolAddress((void**)&p_Wsmb,   g_Wsmb);
    cudaGetSymbolAddress((void**)&p_Vfb,    g_Vfb);
    cudaGetSymbolAddress((void**)&p_xallb,  g_xallb);
    cudaGetSymbolAddress((void**)&p_Wxcatb, g_Wxcatb);
    cudaGetSymbolAddress((void**)&p_WHb,    g_WHb);
    cudaGetSymbolAddress((void**)&p_Wcb,    g_Wcb);
    cudaGetSymbolAddress((void**)&p_Wfcb,   g_Wfcb);
    cudaGetSymbolAddress((void**)&p_Wpb,    g_Wpb);
    cudaGetSymbolAddress((void**)&p_hall,   g_hall);
    cudaGetSymbolAddress((void**)&p_t1all,  g_t1all);
    cudaGetSymbolAddress((void**)&p_o512all,g_o512all);
    cudaGetSymbolAddress((void**)&p_vghm,   g_vghm);
    cudaGetSymbolAddress((void**)&p_zbase,  g_zbase);
    cudaGetSymbolAddress((void**)&p_bbhm,   g_bbhm);
    cudaGetSymbolAddress((void**)&p_bcat,   g_bcat);
    cudaGetSymbolAddress((void**)&p_xpre,   g_xpre);

    static cudaStream_t s2 = nullptr;
    static cudaEvent_t evFork = nullptr, evJoin = nullptr;
    if (!s2) {
        cudaStreamCreateWithFlags(&s2, cudaStreamNonBlocking);
        cudaEventCreateWithFlags(&evFork, cudaEventDisableTiming);
        cudaEventCreateWithFlags(&evJoin, cudaEventDisableTiming);
    }

    auto cvt = [&](cudaStream_t st, const float* in, bf16* out, int n) {
        cvt_bf16_kernel<<<(n / 4 + 255) / 256, 256, 0, st>>>(in, out, n / 4);
    };

    // ---- fork side stream ----
    cudaEventRecord(evFork, 0);
    cudaStreamWaitEvent(s2, evFork, 0);

    // ---- side stream: everything not needed until the tail ----
    cvt(s2, img, p_imgb, BB * NN * CC);
    cvt(s2, Wa,  p_Wab,  DD * CC);
    cvt(s2, Wv,  p_Wvb,  NN * DD);
    cvt(s2, Wg,  p_Wgb,  NN * DD);
    cvt(s2, Wsm, p_Wsmb, NN * DD);
    cvt(s2, WH,  p_WHb,  DD * DD);
    cvt(s2, Wc,  p_Wcb,  DD * DD);
    cvt(s2, Wfc, p_Wfcb, DD * DD);
    cvt(s2, Wp,  p_Wpb,  VV * DD);
    gemm3<1, 2, 0><<<t3grid(BB * NN, DD), 256, 0, s2>>>(p_imgb, CC, p_Wab, CC, ba,
                                                        nullptr, p_Vfb, DD, DD, CC);
    gemm2<0, 0, 0><<<t2grid(BB * NN, NN), 256, 0, s2>>>(p_Vfb, DD, p_Wvb, DD, nullptr,
                                                        p_zbase, nullptr, NN, NN, DD);
    cudaEventRecord(evJoin, s2);

    // ---- main stream: critical chain to the recurrence ----
    mean_kernel<<<(BB * CC + 255) / 256, 256>>>(img);
    build_wbhm_kernel<<<(1536 * CC + 255) / 256, 256>>>(Wb, Whi, Wmi, bb, bhi, bmi);
    build_wxcat_kernel<<<(GDIM * XD1 + 255) / 256, 256>>>(Wih, Wx, bih, bhh);
    build_whci_kernel<<<(GDIM * DD + 255) / 256, 256>>>(Whh, Wh2);
    gemm2<1, 0, 0><<<t2grid(BB, 1536), 256>>>(p_meanb, CC, p_Wbhmb, CC, p_bbhm,
                                              p_vghm, nullptr, 1536, 1536, CC);
    hm_init_kernel<<<(BB * DD + 255) / 256, 256>>>();
    xall_init_kernel<<<(MT * XD1 + 255) / 256, 256>>>(emb, target);
    // xpre (gate-interleaved cols) = xall @ Wxcat'^T + bcat'
    gemm3<0, 0, 0><<<t3grid(MT, GDIM), 256>>>(p_xallb, XD1, p_Wxcatb, XD1, p_bcat,
                                              p_xpre, nullptr, GDIM, GDIM, XD1);

    // serial recurrence: ONE fused kernel per step
    for (int t = 0; t < TT; t++)
        step_fused<<<dim3(8, 2), 256>>>(t);

    // ---- join: tail needs side-stream outputs ----
    cudaStreamWaitEvent(0, evJoin, 0);

    hs_batched<<<dim3(4, MT / 128, 2), 256>>>(bc);
    ghsw_batched<<<dim3(1, MT / 128, 2), 256>>>();
    attn_fused_kernel<<<MT, 128>>>(wh, out_attn);
    gemm3<2, 2, 0><<<t3grid(MT, DD), 256>>>(p_t1all, DD, p_Wfcb, DD, bfc,
                                            nullptr, p_o512all, DD, DD, DD);
    gemm3<0, 0, 1><<<t3grid(MT, VV), 256>>>(p_o512all, DD, p_Wpb, DD, bp,
                                            out_logits, nullptr, VV, VV, DD);
    log_softmax_kernel<<<MT, 256>>>(out_logits);
}

// round 11
// speedup vs baseline: 1.4214x; 1.4214x over previous
#include <cuda_runtime.h>
#include <cuda_bf16.h>
#include <math.h>
#include <stdint.h>

// Problem constants
#define BB 128
#define NN 49
#define CC 2048
#define DD 512
#define EE 512
#define VV 10000
#define TT 20
#define XD1 1024       // x = [vg | we]
#define GDIM 2560      // 4D gates + D gate-linear
#define MT (BB * TT)   // 2560 batched rows

typedef __nv_bfloat16 bf16;

// ---------------- device scratch ----------------
__device__ __align__(16) bf16 g_imgb[BB * NN * CC];
__device__ __align__(16) bf16 g_meanb[BB * CC];
__device__ __align__(16) bf16 g_Wbhmb[1536 * CC];
__device__ __align__(16) bf16 g_Wab[DD * CC];
__device__ __align__(16) bf16 g_Wvb[NN * DD];
__device__ __align__(16) bf16 g_Wgb[NN * DD];
__device__ __align__(16) bf16 g_Wsmb[NN * DD];
__device__ __align__(16) bf16 g_Vfb[BB * NN * DD];
__device__ __align__(16) bf16 g_xallb[MT * XD1];
__device__ __align__(16) bf16 g_Wxcatb[GDIM * XD1];
__device__ __align__(16) bf16 g_Whhcatb[GDIM * DD];
__device__ __align__(16) bf16 g_WHb[DD * DD];
__device__ __align__(16) bf16 g_Wcb[DD * DD];
__device__ __align__(16) bf16 g_Wfcb[DD * DD];
__device__ __align__(16) bf16 g_Wpb[VV * DD];
__device__ __align__(16) bf16 g_hall[(TT + 1) * BB * DD];
__device__ __align__(16) bf16 g_uall[MT * DD];
__device__ __align__(16) bf16 g_Hallb[MT * DD];
__device__ __align__(16) bf16 g_sallb[MT * DD];
__device__ __align__(16) bf16 g_t1all[MT * DD];
__device__ __align__(16) bf16 g_o512all[MT * DD];
// fp32
__device__ __align__(16) float g_vghm[BB * 1536];
__device__ __align__(16) float g_zbase[BB * NN * NN];
__device__ __align__(16) float g_bbhm[1536];
__device__ __align__(16) float g_bcat[GDIM];
__device__ __align__(16) float g_xpre[(size_t)MT * GDIM];
__device__ __align__(16) float g_preact[BB * GDIM];
__device__ __align__(16) float g_m[2][BB * DD];
__device__ __align__(16) float g_gHall[MT * NN];
__device__ __align__(16) float g_sWsall[MT * NN];

__device__ __forceinline__ float sigf(float x) { return 1.0f / (1.0f + expf(-x)); }

__device__ __forceinline__ uint4 ldsm4(uint32_t addr) {
    uint4 r;
    asm volatile("ldmatrix.sync.aligned.m8n8.x4.shared.b16 {%0,%1,%2,%3}, [%4];"
                 : "=r"(r.x), "=r"(r.y), "=r"(r.z), "=r"(r.w) : "r"(addr));
    return r;
}

__device__ __forceinline__ void mma16(float* c, const uint4 a, uint32_t b0, uint32_t b1) {
    asm volatile("mma.sync.aligned.m16n8k16.row.col.f32.bf16.bf16.f32 "
        "{%0,%1,%2,%3}, {%4,%5,%6,%7}, {%8,%9}, {%0,%1,%2,%3};"
        : "+f"(c[0]), "+f"(c[1]), "+f"(c[2]), "+f"(c[3])
        : "r"(a.x), "r"(a.y), "r"(a.z), "r"(a.w), "r"(b0), "r"(b1));
}

// ============ 64x64 bf16 GEMM body (128 threads) — serial recurrence ============
template <int INIT>
__device__ __forceinline__ void gemm64_body(
    const bf16* __restrict__ A, int lda,
    const bf16* __restrict__ W, int ldw,
    const float* __restrict__ Ci,
    float* __restrict__ C, long long ldc, int N, int K)
{
    __shared__ __align__(16) bf16 sA[64 * 40];
    __shared__ __align__(16) bf16 sB[64 * 40];

    const int tid = threadIdx.x;
    const int lane = tid & 31, w = tid >> 5;
    const int wm = (w >> 1) * 32, wn = (w & 1) * 32;
    const int m0 = blockIdx.y * 64, n0 = blockIdx.x * 64;
    const int g = lane >> 2, q = lane & 3;
    const int grow = tid >> 1, gc0 = (tid & 1) * 2;

    const uint32_t baseA = (uint32_t)__cvta_generic_to_shared(sA);
    const uint32_t baseB = (uint32_t)__cvta_generic_to_shared(sB);
    const int rA = wm + (lane & 7) + ((lane >> 3) & 1) * 8;
    const uint32_t offA0 = baseA + (uint32_t)(rA * 40 + (lane >> 4) * 8) * 2;
    const int rB = wn + (lane & 7);
    const uint32_t offB0 = baseB + (uint32_t)(rB * 40 + (lane >> 3) * 8) * 2;

    float acc[2][4][4];
#pragma unroll
    for (int i = 0; i < 2; i++)
#pragma unroll
        for (int j = 0; j < 4; j++)
#pragma unroll
            for (int u = 0; u < 4; u++) acc[i][j][u] = 0.f;

    uint4 pa[2], pb[2];
    auto load_regs = [&](int k0) {
#pragma unroll
        for (int e = 0; e < 2; e++) {
            const int gk = k0 + (gc0 + e) * 8;
            pa[e] = *reinterpret_cast<const uint4*>(A + (size_t)(m0 + grow) * lda + gk);
            pb[e] = *reinterpret_cast<const uint4*>(W + (size_t)(n0 + grow) * ldw + gk);
        }
    };
    auto store_smem = [&]() {
#pragma unroll
        for (int e = 0; e < 2; e++) {
            *reinterpret_cast<uint4*>(&sA[grow * 40 + (gc0 + e) * 8]) = pa[e];
            *reinterpret_cast<uint4*>(&sB[grow * 40 + (gc0 + e) * 8]) = pb[e];
        }
    };

    load_regs(0);
    store_smem();
    for (int k0 = 0; k0 < K; k0 += 32) {
        __syncthreads();
        const bool more = (k0 + 32) < K;
        if (more) load_regs(k0 + 32);
        uint4 bfr[4];
#pragma unroll
        for (int j = 0; j < 4; j++) bfr[j] = ldsm4(offB0 + j * 640);
#pragma unroll
        for (int kt = 0; kt < 2; kt++) {
            uint4 af0 = ldsm4(offA0 + kt * 32);
            uint4 af1 = ldsm4(offA0 + 1280 + kt * 32);
#pragma unroll
            for (int j = 0; j < 4; j++) {
                const uint32_t b0 = kt ? bfr[j].z : bfr[j].x;
                const uint32_t b1 = kt ? bfr[j].w : bfr[j].y;
                mma16(acc[0][j], af0, b0, b1);
                mma16(acc[1][j], af1, b0, b1);
            }
        }
        if (more) {
            __syncthreads();
            store_smem();
        }
    }
#pragma unroll
    for (int i = 0; i < 2; i++) {
        const int r0 = m0 + wm + i * 16 + g;
#pragma unroll
        for (int j = 0; j < 4; j++) {
            const int col = n0 + wn + j * 8 + q * 2;
            float v00 = acc[i][j][0], v01 = acc[i][j][1];
            float v10 = acc[i][j][2], v11 = acc[i][j][3];
            if (INIT) {
                v00 += Ci[(size_t)r0 * ldc + col];
                v01 += Ci[(size_t)r0 * ldc + col + 1];
                v10 += Ci[(size_t)(r0 + 8) * ldc + col];
                v11 += Ci[(size_t)(r0 + 8) * ldc + col + 1];
            }
            C[(size_t)r0 * ldc + col]         = v00;
            C[(size_t)r0 * ldc + col + 1]     = v01;
            C[(size_t)(r0 + 8) * ldc + col]   = v10;
            C[(size_t)(r0 + 8) * ldc + col + 1] = v11;
        }
    }
}

__global__ __launch_bounds__(128) void gemm_preact(
    const bf16* __restrict__ A, const float* __restrict__ Ci)
{
    gemm64_body<1>(A, DD, g_Whhcatb, DD, Ci, g_preact, GDIM, GDIM, DD);
}

// ============ 128x64 bf16 GEMM body (256 threads, 8 warps 4x2) ============
template <int ACT, int OUT, int REMAP>
__device__ __forceinline__ void gemm2_body(
    const bf16* __restrict__ A, int lda,
    const bf16* __restrict__ W, int ldw,
    const float* __restrict__ bias,
    float* __restrict__ C, bf16* __restrict__ Cb,
    long long ldc, int N, int K)
{
    __shared__ __align__(16) bf16 sA[128 * 40];
    __shared__ __align__(16) bf16 sB[64 * 40];

    const int tid = threadIdx.x;
    const int lane = tid & 31, w = tid >> 5;
    const int wm = (w >> 1) * 32, wn = (w & 1) * 32;
    const int m0 = blockIdx.y * 128, n0 = blockIdx.x * 64;
    const int g = lane >> 2, q = lane & 3;
    const int arow = tid >> 1, ac0 = (tid & 1) * 2;
    const int brow = tid >> 2, bc0 = tid & 3;
    const uint4 z4 = make_uint4(0, 0, 0, 0);

    const uint32_t baseA = (uint32_t)__cvta_generic_to_shared(sA);
    const uint32_t baseB = (uint32_t)__cvta_generic_to_shared(sB);
    const int rA = wm + (lane & 7) + ((lane >> 3) & 1) * 8;
    const uint32_t offA0 = baseA + (uint32_t)(rA * 40 + (lane >> 4) * 8) * 2;
    const int rB = wn + (lane & 7);
    const uint32_t offB0 = baseB + (uint32_t)(rB * 40 + (lane >> 3) * 8) * 2;

    float acc[2][4][4];
#pragma unroll
    for (int i = 0; i < 2; i++)
#pragma unroll
        for (int j = 0; j < 4; j++)
#pragma unroll
            for (int u = 0; u < 4; u++) acc[i][j][u] = 0.f;

    uint4 pa[2], pb;
    auto load_regs = [&](int k0) {
#pragma unroll
        for (int e = 0; e < 2; e++)
            pa[e] = *reinterpret_cast<const uint4*>(A + (size_t)(m0 + arow) * lda + k0 + (ac0 + e) * 8);
        pb = (n0 + brow < N)
            ? *reinterpret_cast<const uint4*>(W + (size_t)(n0 + brow) * ldw + k0 + bc0 * 8)
            : z4;
    };
    auto store_smem = [&]() {
#pragma unroll
        for (int e = 0; e < 2; e++)
            *reinterpret_cast<uint4*>(&sA[arow * 40 + (ac0 + e) * 8]) = pa[e];
        *reinterpret_cast<uint4*>(&sB[brow * 40 + bc0 * 8]) = pb;
    };

    load_regs(0);
    store_smem();

    for (int k0 = 0; k0 < K; k0 += 32) {
        __syncthreads();
        const bool more = (k0 + 32) < K;
        if (more) load_regs(k0 + 32);

        uint4 bfr[4];
#pragma unroll
        for (int j = 0; j < 4; j++) bfr[j] = ldsm4(offB0 + j * 640);
#pragma unroll
        for (int kt = 0; kt < 2; kt++) {
            uint4 af0 = ldsm4(offA0 + kt * 32);
            uint4 af1 = ldsm4(offA0 + 1280 + kt * 32);
#pragma unroll
            for (int j = 0; j < 4; j++) {
                const uint32_t b0 = kt ? bfr[j].z : bfr[j].x;
                const uint32_t b1 = kt ? bfr[j].w : bfr[j].y;
                mma16(acc[0][j], af0, b0, b1);
                mma16(acc[1][j], af1, b0, b1);
            }
        }
        if (more) {
            __syncthreads();
            store_smem();
        }
    }

#pragma unroll
    for (int i = 0; i < 2; i++) {
        const int r0 = m0 + wm + i * 16 + g;
        const long long orow0 = REMAP ? (long long)((r0 & 127) * TT + (r0 >> 7)) : (long long)r0;
        const long long orow1 = REMAP ? (long long)(((r0 + 8) & 127) * TT + ((r0 + 8) >> 7)) : (long long)(r0 + 8);
#pragma unroll
        for (int j = 0; j < 4; j++) {
            const int col = n0 + wn + j * 8 + q * 2;
            float b0v = 0.f, b1v = 0.f;
            if (bias) {
                if (col < N)     b0v = bias[col];
                if (col + 1 < N) b1v = bias[col + 1];
            }
            float v00 = acc[i][j][0] + b0v, v01 = acc[i][j][1] + b1v;
            float v10 = acc[i][j][2] + b0v, v11 = acc[i][j][3] + b1v;
            if (ACT == 1) {
                v00 = fmaxf(v00, 0.f); v01 = fmaxf(v01, 0.f);
                v10 = fmaxf(v10, 0.f); v11 = fmaxf(v11, 0.f);
            } else if (ACT == 2) {
                v00 = tanhf(v00); v01 = tanhf(v01);
                v10 = tanhf(v10); v11 = tanhf(v11);
            }
            if (col < N) {
                if (OUT == 0) { C[orow0 * ldc + col] = v00; C[orow1 * ldc + col] = v10; }
                else { Cb[orow0 * ldc + col] = __float2bfloat16(v00);
                       Cb[orow1 * ldc + col] = __float2bfloat16(v10); }
            }
            if (col + 1 < N) {
                if (OUT == 0) { C[orow0 * ldc + col + 1] = v01; C[orow1 * ldc + col + 1] = v11; }
                else { Cb[orow0 * ldc + col + 1] = __float2bfloat16(v01);
                       Cb[orow1 * ldc + col + 1] = __float2bfloat16(v11); }
            }
        }
    }
}

template <int ACT, int OUT, int REMAP>
__global__ __launch_bounds__(256) void gemm2(
    const bf16* __restrict__ A, int lda,
    const bf16* __restrict__ W, int ldw,
    const float* __restrict__ bias,
    float* __restrict__ C, bf16* __restrict__ Cb, long long ldc, int N, int K)
{
    gemm2_body<ACT, OUT, REMAP>(A, lda, W, ldw, bias, C, Cb, ldc, N, K);
}

// ============ 128x128 bf16 GEMM (256 threads) — logits only this round ============
template <int ACT, int OUT, int REMAP>
__global__ __launch_bounds__(256) void gemm3(
    const bf16* __restrict__ A, int lda,
    const bf16* __restrict__ W, int ldw,
    const float* __restrict__ bias,
    float* __restrict__ C, bf16* __restrict__ Cb, long long ldc, int N, int K)
{
    __shared__ __align__(16) bf16 sA[128 * 40];
    __shared__ __align__(16) bf16 sB[128 * 40];

    const int tid = threadIdx.x;
    const int lane = tid & 31, w = tid >> 5;
    const int wm = (w >> 1) * 32, wn = (w & 1) * 64;
    const int m0 = blockIdx.y * 128, n0 = blockIdx.x * 128;
    const int g = lane >> 2, q = lane & 3;
    const int arow = tid >> 1, ac0 = (tid & 1) * 2;
    const uint4 z4 = make_uint4(0, 0, 0, 0);

    const uint32_t baseA = (uint32_t)__cvta_generic_to_shared(sA);
    const uint32_t baseB = (uint32_t)__cvta_generic_to_shared(sB);
    const int rA = wm + (lane & 7) + ((lane >> 3) & 1) * 8;
    const uint32_t offA0 = baseA + (uint32_t)(rA * 40 + (lane >> 4) * 8) * 2;
    const int rB = wn + (lane & 7);
    const uint32_t offB0 = baseB + (uint32_t)(rB * 40 + (lane >> 3) * 8) * 2;

    float acc[2][8][4];
#pragma unroll
    for (int i = 0; i < 2; i++)
#pragma unroll
        for (int j = 0; j < 8; j++)
#pragma unroll
            for (int u = 0; u < 4; u++) acc[i][j][u] = 0.f;

    uint4 pa[2], pb[2];
    auto load_regs = [&](int k0) {
#pragma unroll
        for (int e = 0; e < 2; e++) {
            pa[e] = *reinterpret_cast<const uint4*>(A + (size_t)(m0 + arow) * lda + k0 + (ac0 + e) * 8);
            pb[e] = (n0 + arow < N)
                ? *reinterpret_cast<const uint4*>(W + (size_t)(n0 + arow) * ldw + k0 + (ac0 + e) * 8)
                : z4;
        }
    };
    auto store_smem = [&]() {
#pragma unroll
        for (int e = 0; e < 2; e++) {
            *reinterpret_cast<uint4*>(&sA[arow * 40 + (ac0 + e) * 8]) = pa[e];
            *reinterpret_cast<uint4*>(&sB[arow * 40 + (ac0 + e) * 8]) = pb[e];
        }
    };

    load_regs(0);
    store_smem();

    for (int k0 = 0; k0 < K; k0 += 32) {
        __syncthreads();
        const bool more = (k0 + 32) < K;
        if (more) load_regs(k0 + 32);

        uint4 bfr[8];
#pragma unroll
        for (int j = 0; j < 8; j++) bfr[j] = ldsm4(offB0 + j * 640);
#pragma unroll
        for (int kt = 0; kt < 2; kt++) {
            uint4 af0 = ldsm4(offA0 + kt * 32);
            uint4 af1 = ldsm4(offA0 + 1280 + kt * 32);
#pragma unroll
            for (int j = 0; j < 8; j++) {
                const uint32_t b0 = kt ? bfr[j].z : bfr[j].x;
                const uint32_t b1 = kt ? bfr[j].w : bfr[j].y;
                mma16(acc[0][j], af0, b0, b1);
                mma16(acc[1][j], af1, b0, b1);
            }
        }
        if (more) {
            __syncthreads();
            store_smem();
        }
    }

#pragma unroll
    for (int i = 0; i < 2; i++) {
        const int r0 = m0 + wm + i * 16 + g;
        const long long orow0 = REMAP ? (long long)((r0 & 127) * TT + (r0 >> 7)) : (long long)r0;
        const long long orow1 = REMAP ? (long long)(((r0 + 8) & 127) * TT + ((r0 + 8) >> 7)) : (long long)(r0 + 8);
#pragma unroll
        for (int j = 0; j < 8; j++) {
            const int col = n0 + wn + j * 8 + q * 2;
            float b0v = 0.f, b1v = 0.f;
            if (bias) {
                if (col < N)     b0v = bias[col];
                if (col + 1 < N) b1v = bias[col + 1];
            }
            float v00 = acc[i][j][0] + b0v, v01 = acc[i][j][1] + b1v;
            float v10 = acc[i][j][2] + b0v, v11 = acc[i][j][3] + b1v;
            if (ACT == 1) {
                v00 = fmaxf(v00, 0.f); v01 = fmaxf(v01, 0.f);
                v10 = fmaxf(v10, 0.f); v11 = fmaxf(v11, 0.f);
            } else if (ACT == 2) {
                v00 = tanhf(v00); v01 = tanhf(v01);
                v10 = tanhf(v10); v11 = tanhf(v11);
            }
            if (col < N) {
                if (OUT == 0) { C[orow0 * ldc + col] = v00; C[orow1 * ldc + col] = v10; }
                else { Cb[orow0 * ldc + col] = __float2bfloat16(v00);
                       Cb[orow1 * ldc + col] = __float2bfloat16(v10); }
            }
            if (col + 1 < N) {
                if (OUT == 0) { C[orow0 * ldc + col + 1] = v01; C[orow1 * ldc + col + 1] = v11; }
                else { Cb[orow0 * ldc + col + 1] = __float2bfloat16(v01);
                       Cb[orow1 * ldc + col + 1] = __float2bfloat16(v11); }
            }
        }
    }
}

__global__ __launch_bounds__(256) void hs_batched(const float* __restrict__ bc)
{
    if (blockIdx.z == 0)
        gemm2_body<1, 2, 0>(g_hall + BB * DD, DD, g_WHb, DD, nullptr, nullptr, g_Hallb, DD, DD, DD);
    else
        gemm2_body<1, 2, 0>(g_uall, DD, g_Wcb, DD, bc, nullptr, g_sallb, DD, DD, DD);
}

__global__ __launch_bounds__(256) void ghsw_batched()
{
    if (blockIdx.z == 0)
        gemm2_body<0, 0, 0>(g_Hallb, DD, g_Wgb, DD, nullptr, g_gHall, nullptr, NN, NN, DD);
    else
        gemm2_body<0, 0, 0>(g_sallb, DD, g_Wsmb, DD, nullptr, g_sWsall, nullptr, NN, NN, DD);
}

// ---------------- conversion / setup kernels ----------------
__global__ void cvt_bf16_kernel(const float* __restrict__ in, bf16* __restrict__ out, int n4)
{
    int idx = blockIdx.x * blockDim.x + threadIdx.x;
    if (idx >= n4) return;
    float4 v = reinterpret_cast<const float4*>(in)[idx];
    reinterpret_cast<__nv_bfloat162*>(out)[idx * 2]     = __floats2bfloat162_rn(v.x, v.y);
    reinterpret_cast<__nv_bfloat162*>(out)[idx * 2 + 1] = __floats2bfloat162_rn(v.z, v.w);
}

__global__ void mean_kernel(const float* __restrict__ img)
{
    int idx = blockIdx.x * blockDim.x + threadIdx.x;
    if (idx >= BB * CC) return;
    int b = idx / CC, c = idx % CC;
    const float* p = img + (size_t)b * NN * CC + c;
    float s = 0.f;
#pragma unroll 7
    for (int n = 0; n < NN; n++) s += p[(size_t)n * CC];
    g_meanb[idx] = __float2bfloat16(s * (1.0f / NN));
}

__global__ void build_wbhm_kernel(const float* __restrict__ Wb, const float* __restrict__ Whi,
                                  const float* __restrict__ Wmi,
                                  const float* __restrict__ bb, const float* __restrict__ bhi,
                                  const float* __restrict__ bmi)
{
    int idx = blockIdx.x * blockDim.x + threadIdx.x;
    if (idx >= 1536 * CC) return;
    int r = idx / CC, c = idx % CC;
    float v;
    if (r < 512)       v = Wb[(size_t)r * CC + c];
    else if (r < 1024) v = Whi[(size_t)(r - 512) * CC + c];
    else               v = Wmi[(size_t)(r - 1024) * CC + c];
    g_Wbhmb[idx] = __float2bfloat16(v);
    if (c == 0) g_bbhm[r] = (r < 512) ? bb[r] : (r < 1024 ? bhi[r - 512] : bmi[r - 1024]);
}

__global__ void build_wxcat_kernel(const float* __restrict__ Wih, const float* __restrict__ Wx,
                                   const float* __restrict__ bih, const float* __restrict__ bhh)
{
    int idx = blockIdx.x * blockDim.x + threadIdx.x;
    if (idx >= GDIM * XD1) return;
    int r = idx / XD1, c = idx % XD1;
    float v = (r < 2048) ? Wih[(size_t)r * XD1 + c] : Wx[(size_t)(r - 2048) * XD1 + c];
    g_Wxcatb[idx] = __float2bfloat16(v);
    if (c == 0) g_bcat[r] = (r < 2048) ? (bih[r] + bhh[r]) : 0.f;
}

__global__ void build_whhcat_kernel(const float* __restrict__ Whh, const float* __restrict__ Wh2)
{
    int idx = blockIdx.x * blockDim.x + threadIdx.x;
    if (idx >= GDIM * DD) return;
    int r = idx / DD, c = idx % DD;
    float v = (r < 2048) ? Whh[(size_t)r * DD + c] : Wh2[(size_t)(r - 2048) * DD + c];
    g_Whhcatb[idx] = __float2bfloat16(v);
}

__global__ void hm_init_kernel()
{
    int idx = blockIdx.x * blockDim.x + threadIdx.x;
    if (idx >= BB * DD) return;
    int b = idx >> 9, d = idx & 511;
    g_hall[idx] = __float2bfloat16(g_vghm[b * 1536 + 512 + d]);
    g_m[0][idx] = g_vghm[b * 1536 + 1024 + d];
}

__global__ void xall_init_kernel(const float* __restrict__ emb, const int* __restrict__ target)
{
    int idx = blockIdx.x * blockDim.x + threadIdx.x;
    if (idx >= MT * XD1) return;
    int j = idx % XD1;
    int tb = idx / XD1;
    int b = tb % BB;
    int t = tb / BB;
    float v;
    if (j < 512) v = g_vghm[b * 1536 + j];
    else if (t == 0) v = 0.f;
    else {
        int tok = target[b * TT + t - 1];
        v = emb[(size_t)tok * EE + (j - 512)];
    }
    g_xallb[((size_t)t * BB + b) * XD1 + j] = __float2bfloat16(v);
}

__global__ void lstm_elem_kernel(int t)
{
    int idx = blockIdx.x * blockDim.x + threadIdx.x;
    if (idx >= BB * DD) return;
    int b = idx >> 9, d = idx & 511;
    int cur = t & 1, nxt = cur ^ 1;
    const float* p = g_preact + (size_t)b * GDIM;
    float gi = p[d], gf = p[512 + d], gg = p[1024 + d], go = p[1536 + d], gl = p[2048 + d];
    float m2 = sigf(gf) * g_m[cur][idx] + sigf(gi) * tanhf(gg);
    float tm2 = tanhf(m2);
    g_m[nxt][idx] = m2;
    g_hall[(size_t)(t + 1) * BB * DD + idx] = __float2bfloat16(sigf(go) * tm2);
    g_uall[(size_t)t * BB * DD + idx] = __float2bfloat16(sigf(gl) * tm2);
}

// batched attention
__global__ void attn_fused_kernel(const float* __restrict__ wh, float* __restrict__ attn_out)
{
    const int r = blockIdx.x;            // t*128 + b
    const int t = r >> 7, b = r & 127;
    __shared__ float gHs[49], sWss[49], zsh[50], wsh[49];
    int tid = threadIdx.x;  // 128

    if (tid < 49) {
        gHs[tid] = g_gHall[r * 49 + tid];
        sWss[tid] = g_sWsall[r * 49 + tid];
        wsh[tid] = wh[tid];
    }
    __syncthreads();

    if (tid < 49) {
        const float* zb = g_zbase + ((size_t)b * 49 + tid) * 49;
        float acc = 0.f;
#pragma unroll 7
        for (int k = 0; k < 49; k++) acc += tanhf(zb[k] + gHs[k]) * wsh[k];
        zsh[tid] = acc;
    } else if (tid == 49) {
        float acc = 0.f;
#pragma unroll 7
        for (int k = 0; k < 49; k++) acc += tanhf(sWss[k] + gHs[k]) * wsh[k];
        zsh[49] = acc;
    }
    __syncthreads();

    if (tid == 0) {
        float mx = -1e30f;
        for (int i = 0; i < 50; i++) mx = fmaxf(mx, zsh[i]);
        float sum = 0.f;
        for (int i = 0; i < 50; i++) { zsh[i] = expf(zsh[i] - mx); sum += zsh[i]; }
        float inv = 1.f / sum;
        for (int i = 0; i < 50; i++) zsh[i] *= inv;
    }
    __syncthreads();

    if (tid < 49) attn_out[((size_t)b * TT + t) * 49 + tid] = zsh[tid];

    const float a50 = zsh[49];
    const bf16* srow = g_sallb + (size_t)r * 512;
    const bf16* Hrow = g_Hallb + (size_t)r * 512;
#pragma unroll
    for (int e = 0; e < 4; e++) {
        int d = tid + e * 128;
        float acc = a50 * __bfloat162float(srow[d]);
#pragma unroll 7
        for (int n = 0; n < 49; n++)
            acc = fmaf(zsh[n], __bfloat162float(g_Vfb[((size_t)b * 49 + n) * 512 + d]), acc);
        g_t1all[(size_t)r * 512 + d] = __float2bfloat16(__bfloat162float(Hrow[d]) + acc);
    }
}

// online single-pass max+sum log-softmax, float4
__global__ void log_softmax_kernel(float* __restrict__ logits)
{
    const int row = blockIdx.x;
    float4* x4 = reinterpret_cast<float4*>(logits + (size_t)row * VV);
    const int tid = threadIdx.x;  // 256
    float mx = -1e30f, sm = 0.f;
    for (int i = tid; i < VV / 4; i += 256) {
        float4 v = x4[i];
        float m2 = fmaxf(fmaxf(v.x, v.y), fmaxf(v.z, v.w));
        if (m2 > mx) { sm *= expf(mx - m2); mx = m2; }
        sm += expf(v.x - mx) + expf(v.y - mx) + expf(v.z - mx) + expf(v.w - mx);
    }
    __shared__ float smx[256], ssm[256];
    smx[tid] = mx; ssm[tid] = sm;
    __syncthreads();
    for (int s = 128; s; s >>= 1) {
        if (tid < s) {
            float m2 = fmaxf(smx[tid], smx[tid + s]);
            ssm[tid] = ssm[tid] * expf(smx[tid] - m2) + ssm[tid + s] * expf(smx[tid + s] - m2);
            smx[tid] = m2;
        }
        __syncthreads();
    }
    const float lse = smx[0] + logf(ssm[0]);
    for (int i = tid; i < VV / 4; i += 256) {
        float4 v = x4[i];
        v.x -= lse; v.y -= lse; v.z -= lse; v.w -= lse;
        x4[i] = v;
    }
}

// ---------------- host ----------------
static inline dim3 t2grid(int M, int N) { return dim3((N + 63) / 64, M / 128); }
static inline dim3 t3grid(int M, int N) { return dim3((N + 127) / 128, M / 128); }

extern "C" void kernel_launch(void* const* d_in, const int* in_sizes, int n_in,
                              void* d_out, int out_size)
{
    const float* img    = (const float*)d_in[0];
    const int*   target = (const int*)d_in[1];
    const float* emb    = (const float*)d_in[2];
    const float* Wa  = (const float*)d_in[3];  const float* ba  = (const float*)d_in[4];
    const float* Wb  = (const float*)d_in[5];  const float* bb  = (const float*)d_in[6];
    const float* Whi = (const float*)d_in[7];  const float* bhi = (const float*)d_in[8];
    const float* Wmi = (const float*)d_in[9];  const float* bmi = (const float*)d_in[10];
    const float* Wih = (const float*)d_in[11]; const float* bih = (const float*)d_in[12];
    const float* Whh = (const float*)d_in[13]; const float* bhh = (const float*)d_in[14];
    const float* Wv  = (const float*)d_in[15];
    const float* Wg  = (const float*)d_in[16];
    const float* wh  = (const float*)d_in[17];
    const float* WH  = (const float*)d_in[18];
    const float* Wx  = (const float*)d_in[19];
    const float* Wh2 = (const float*)d_in[20];
    const float* Wsm = (const float*)d_in[21];
    const float* Wc  = (const float*)d_in[22]; const float* bc  = (const float*)d_in[23];
    const float* Wfc = (const float*)d_in[24]; const float* bfc = (const float*)d_in[25];
    const float* Wp  = (const float*)d_in[26]; const float* bp  = (const float*)d_in[27];

    float* out_logits = (float*)d_out;                               // [B,T,VOC]
    float* out_attn   = (float*)d_out + (size_t)BB * TT * VV;        // [B,T,N]

    bf16 *p_imgb, *p_meanb, *p_Wbhmb, *p_Wab, *p_Wvb, *p_Wgb, *p_Wsmb, *p_Vfb, *p_xallb;
    bf16 *p_Wxcatb, *p_WHb, *p_Wcb, *p_Wfcb, *p_Wpb, *p_hall, *p_t1all, *p_o512all;
    float *p_vghm, *p_zbase, *p_bbhm, *p_bcat, *p_xpre;
    cudaGetSymbolAddress((void**)&p_imgb,   g_imgb);
    cudaGetSymbolAddress((void**)&p_meanb,  g_meanb);
    cudaGetSymbolAddress((void**)&p_Wbhmb,  g_Wbhmb);
    cudaGetSymbolAddress((void**)&p_Wab,    g_Wab);
    cudaGetSymbolAddress((void**)&p_Wvb,    g_Wvb);
    cudaGetSymbolAddress((void**)&p_Wgb,    g_Wgb);
    cudaGetSymbolAddress((void**)&p_Wsmb,   g_Wsmb);
    cudaGetSymbolAddress((void**)&p_Vfb,    g_Vfb);
    cudaGetSymbolAddress((void**)&p_xallb,  g_xallb);
    cudaGetSymbolAddress((void**)&p_Wxcatb, g_Wxcatb);
    cudaGetSymbolAddress((void**)&p_WHb,    g_WHb);
    cudaGetSymbolAddress((void**)&p_Wcb,    g_Wcb);
    cudaGetSymbolAddress((void**)&p_Wfcb,   g_Wfcb);
    cudaGetSymbolAddress((void**)&p_Wpb,    g_Wpb);
    cudaGetSymbolAddress((void**)&p_hall,   g_hall);
    cudaGetSymbolAddress((void**)&p_t1all,  g_t1all);
    cudaGetSymbolAddress((void**)&p_o512all,g_o512all);
    cudaGetSymbolAddress((void**)&p_vghm,   g_vghm);
    cudaGetSymbolAddress((void**)&p_zbase,  g_zbase);
    cudaGetSymbolAddress((void**)&p_bbhm,   g_bbhm);
    cudaGetSymbolAddress((void**)&p_bcat,   g_bcat);
    cudaGetSymbolAddress((void**)&p_xpre,   g_xpre);

    // one-time side stream + fork/join events (host resources; no device alloc)
    static cudaStream_t s2 = nullptr;
    static cudaEvent_t evFork = nullptr, evJoin = nullptr;
    if (!s2) {
        cudaStreamCreateWithFlags(&s2, cudaStreamNonBlocking);
        cudaEventCreateWithFlags(&evFork, cudaEventDisableTiming);
        cudaEventCreateWithFlags(&evJoin, cudaEventDisableTiming);
    }

    auto cvt = [&](cudaStream_t st, const float* in, bf16* out, int n) {
        cvt_bf16_kernel<<<(n / 4 + 255) / 256, 256, 0, st>>>(in, out, n / 4);
    };

    // ---- fork side stream ----
    cudaEventRecord(evFork, 0);
    cudaStreamWaitEvent(s2, evFork, 0);

    // ---- side stream: everything not needed until the tail ----
    cvt(s2, img, p_imgb, BB * NN * CC);
    cvt(s2, Wa,  p_Wab,  DD * CC);
    cvt(s2, Wv,  p_Wvb,  NN * DD);
    cvt(s2, Wg,  p_Wgb,  NN * DD);
    cvt(s2, Wsm, p_Wsmb, NN * DD);
    cvt(s2, WH,  p_WHb,  DD * DD);
    cvt(s2, Wc,  p_Wcb,  DD * DD);
    cvt(s2, Wfc, p_Wfcb, DD * DD);
    cvt(s2, Wp,  p_Wpb,  VV * DD);
    // Vf = relu(imgb @ Wa^T + ba)  (bf16)
    gemm2<1, 2, 0><<<t2grid(BB * NN, DD), 256, 0, s2>>>(p_imgb, CC, p_Wab, CC, ba,
                                                        nullptr, p_Vfb, DD, DD, CC);
    // zbase = Vfb @ Wv^T  (fp32)
    gemm2<0, 0, 0><<<t2grid(BB * NN, NN), 256, 0, s2>>>(p_Vfb, DD, p_Wvb, DD, nullptr,
                                                        p_zbase, nullptr, NN, NN, DD);
    cudaEventRecord(evJoin, s2);

    // ---- main stream: critical chain to the recurrence ----
    mean_kernel<<<(BB * CC + 255) / 256, 256>>>(img);
    build_wbhm_kernel<<<(1536 * CC + 255) / 256, 256>>>(Wb, Whi, Wmi, bb, bhi, bmi);
    build_wxcat_kernel<<<(GDIM * XD1 + 255) / 256, 256>>>(Wih, Wx, bih, bhh);
    build_whhcat_kernel<<<(GDIM * DD + 255) / 256, 256>>>(Whh, Wh2);
    // [vg|h0|m0] = relu(mean @ Wbhm^T + bbhm)
    gemm2<1, 0, 0><<<t2grid(BB, 1536), 256>>>(p_meanb, CC, p_Wbhmb, CC, p_bbhm,
                                              p_vghm, nullptr, 1536, 1536, CC);
    hm_init_kernel<<<(BB * DD + 255) / 256, 256>>>();
    xall_init_kernel<<<(MT * XD1 + 255) / 256, 256>>>(emb, target);
    // xpre = xall @ Wxcat^T + bcat  (all timesteps)
    gemm2<0, 0, 0><<<t2grid(MT, GDIM), 256>>>(p_xallb, XD1, p_Wxcatb, XD1, p_bcat,
                                              p_xpre, nullptr, GDIM, GDIM, XD1);

    // serial recurrence (overlaps with side stream)
    for (int t = 0; t < TT; t++) {
        gemm_preact<<<dim3(GDIM / 64, 2), 128>>>(p_hall + (size_t)t * BB * DD,
                                                 p_xpre + (size_t)t * BB * GDIM);
        lstm_elem_kernel<<<(BB * DD + 255) / 256, 256>>>(t);
    }

    // ---- join: tail needs side-stream outputs (Vfb, zbase, weight cvts) ----
    cudaStreamWaitEvent(0, evJoin, 0);

    hs_batched<<<dim3(8, MT / 128, 2), 256>>>(bc);
    ghsw_batched<<<dim3(1, MT / 128, 2), 256>>>();
    attn_fused_kernel<<<MT, 128>>>(wh, out_attn);
    gemm2<2, 2, 0><<<t2grid(MT, DD), 256>>>(p_t1all, DD, p_Wfcb, DD, bfc,
                                            nullptr, p_o512all, DD, DD, DD);
    // logits: 128x128-tile gemm3 (the ONLY change vs Round 9)
    gemm3<0, 0, 1><<<t3grid(MT, VV), 256>>>(p_o512all, DD, p_Wpb, DD, bp,
                                            out_logits, nullptr, VV, VV, DD);
    log_softmax_kernel<<<MT, 256>>>(out_logits);
}

// round 12
// speedup vs baseline: 1.5617x; 1.0987x over previous
#include <cuda_runtime.h>
#include <cuda_bf16.h>
#include <math.h>
#include <stdint.h>

// Problem constants
#define BB 128
#define NN 49
#define CC 2048
#define DD 512
#define EE 512
#define VV 10000
#define TT 20
#define XD1 1024       // x = [vg | we]
#define GDIM 2560      // 4D gates + D gate-linear
#define MT (BB * TT)   // 2560 batched rows
#define SKR 4          // split-K for serial preact

typedef __nv_bfloat16 bf16;

// ---------------- device scratch ----------------
__device__ __align__(16) bf16 g_imgb[BB * NN * CC];
__device__ __align__(16) bf16 g_meanb[BB * CC];
__device__ __align__(16) bf16 g_Wbhmb[1536 * CC];
__device__ __align__(16) bf16 g_Wab[DD * CC];
__device__ __align__(16) bf16 g_Wvb[NN * DD];
__device__ __align__(16) bf16 g_Wgb[NN * DD];
__device__ __align__(16) bf16 g_Wsmb[NN * DD];
__device__ __align__(16) bf16 g_Vfb[BB * NN * DD];
__device__ __align__(16) bf16 g_xallb[MT * XD1];
__device__ __align__(16) bf16 g_Wxcatb[GDIM * XD1];
__device__ __align__(16) bf16 g_Whhcatb[GDIM * DD];
__device__ __align__(16) bf16 g_WHb[DD * DD];
__device__ __align__(16) bf16 g_Wcb[DD * DD];
__device__ __align__(16) bf16 g_Wfcb[DD * DD];
__device__ __align__(16) bf16 g_Wpb[VV * DD];
__device__ __align__(16) bf16 g_hall[(TT + 1) * BB * DD];
__device__ __align__(16) bf16 g_uall[MT * DD];
__device__ __align__(16) bf16 g_Hallb[MT * DD];
__device__ __align__(16) bf16 g_sallb[MT * DD];
__device__ __align__(16) bf16 g_t1all[MT * DD];
__device__ __align__(16) bf16 g_o512all[MT * DD];
// fp32
__device__ __align__(16) float g_vghm[BB * 1536];
__device__ __align__(16) float g_zbase[BB * NN * NN];
__device__ __align__(16) float g_bbhm[1536];
__device__ __align__(16) float g_bcat[GDIM];
__device__ __align__(16) float g_xpre[(size_t)MT * GDIM];
__device__ __align__(16) float g_pre_part[SKR][BB * GDIM];
__device__ __align__(16) float g_m[2][BB * DD];
__device__ __align__(16) float g_gHall[MT * NN];
__device__ __align__(16) float g_sWsall[MT * NN];

__device__ __forceinline__ float sigf(float x) { return 1.0f / (1.0f + expf(-x)); }

__device__ __forceinline__ uint4 ldsm4(uint32_t addr) {
    uint4 r;
    asm volatile("ldmatrix.sync.aligned.m8n8.x4.shared.b16 {%0,%1,%2,%3}, [%4];"
                 : "=r"(r.x), "=r"(r.y), "=r"(r.z), "=r"(r.w) : "r"(addr));
    return r;
}

__device__ __forceinline__ void mma16(float* c, const uint4 a, uint32_t b0, uint32_t b1) {
    asm volatile("mma.sync.aligned.m16n8k16.row.col.f32.bf16.bf16.f32 "
        "{%0,%1,%2,%3}, {%4,%5,%6,%7}, {%8,%9}, {%0,%1,%2,%3};"
        : "+f"(c[0]), "+f"(c[1]), "+f"(c[2]), "+f"(c[3])
        : "r"(a.x), "r"(a.y), "r"(a.z), "r"(a.w), "r"(b0), "r"(b1));
}

// ============ split-K serial preact: 64x64 tile, K-slice = 128 ============
// grid (GDIM/64, 2, SKR); writes partials to g_pre_part[z].
__global__ __launch_bounds__(128) void gemm_preact_sk(
    const bf16* __restrict__ A)   // h_t  [128, 512]
{
    __shared__ __align__(16) bf16 sA[64 * 40];
    __shared__ __align__(16) bf16 sB[64 * 40];

    const int tid = threadIdx.x;
    const int lane = tid & 31, w = tid >> 5;
    const int wm = (w >> 1) * 32, wn = (w & 1) * 32;
    const int m0 = blockIdx.y * 64, n0 = blockIdx.x * 64;
    const int kb = blockIdx.z * (DD / SKR);      // 128-wide K slice
    const int g = lane >> 2, q = lane & 3;
    const int grow = tid >> 1, gc0 = (tid & 1) * 2;

    const uint32_t baseA = (uint32_t)__cvta_generic_to_shared(sA);
    const uint32_t baseB = (uint32_t)__cvta_generic_to_shared(sB);
    const int rA = wm + (lane & 7) + ((lane >> 3) & 1) * 8;
    const uint32_t offA0 = baseA + (uint32_t)(rA * 40 + (lane >> 4) * 8) * 2;
    const int rB = wn + (lane & 7);
    const uint32_t offB0 = baseB + (uint32_t)(rB * 40 + (lane >> 3) * 8) * 2;

    float acc[2][4][4];
#pragma unroll
    for (int i = 0; i < 2; i++)
#pragma unroll
        for (int j = 0; j < 4; j++)
#pragma unroll
            for (int u = 0; u < 4; u++) acc[i][j][u] = 0.f;

    uint4 pa[2], pb[2];
    auto load_regs = [&](int k0) {
#pragma unroll
        for (int e = 0; e < 2; e++) {
            const int gk = kb + k0 + (gc0 + e) * 8;
            pa[e] = *reinterpret_cast<const uint4*>(A + (size_t)(m0 + grow) * DD + gk);
            pb[e] = *reinterpret_cast<const uint4*>(g_Whhcatb + (size_t)(n0 + grow) * DD + gk);
        }
    };
    auto store_smem = [&]() {
#pragma unroll
        for (int e = 0; e < 2; e++) {
            *reinterpret_cast<uint4*>(&sA[grow * 40 + (gc0 + e) * 8]) = pa[e];
            *reinterpret_cast<uint4*>(&sB[grow * 40 + (gc0 + e) * 8]) = pb[e];
        }
    };

    load_regs(0);
    store_smem();
#pragma unroll
    for (int k0 = 0; k0 < DD / SKR; k0 += 32) {
        __syncthreads();
        const bool more = (k0 + 32) < DD / SKR;
        if (more) load_regs(k0 + 32);
        uint4 bfr[4];
#pragma unroll
        for (int j = 0; j < 4; j++) bfr[j] = ldsm4(offB0 + j * 640);
#pragma unroll
        for (int kt = 0; kt < 2; kt++) {
            uint4 af0 = ldsm4(offA0 + kt * 32);
            uint4 af1 = ldsm4(offA0 + 1280 + kt * 32);
#pragma unroll
            for (int j = 0; j < 4; j++) {
                const uint32_t b0 = kt ? bfr[j].z : bfr[j].x;
                const uint32_t b1 = kt ? bfr[j].w : bfr[j].y;
                mma16(acc[0][j], af0, b0, b1);
                mma16(acc[1][j], af1, b0, b1);
            }
        }
        if (more) {
            __syncthreads();
            store_smem();
        }
    }
    float* Cz = g_pre_part[blockIdx.z];
#pragma unroll
    for (int i = 0; i < 2; i++) {
        const int r0 = m0 + wm + i * 16 + g;
#pragma unroll
        for (int j = 0; j < 4; j++) {
            const int col = n0 + wn + j * 8 + q * 2;
            Cz[(size_t)r0 * GDIM + col]           = acc[i][j][0];
            Cz[(size_t)r0 * GDIM + col + 1]       = acc[i][j][1];
            Cz[(size_t)(r0 + 8) * GDIM + col]     = acc[i][j][2];
            Cz[(size_t)(r0 + 8) * GDIM + col + 1] = acc[i][j][3];
        }
    }
}

// ============ 128x64 bf16 GEMM body (256 threads, 8 warps 4x2) ============
template <int ACT, int OUT, int REMAP>
__device__ __forceinline__ void gemm2_body(
    const bf16* __restrict__ A, int lda,
    const bf16* __restrict__ W, int ldw,
    const float* __restrict__ bias,
    float* __restrict__ C, bf16* __restrict__ Cb,
    long long ldc, int N, int K)
{
    __shared__ __align__(16) bf16 sA[128 * 40];
    __shared__ __align__(16) bf16 sB[64 * 40];

    const int tid = threadIdx.x;
    const int lane = tid & 31, w = tid >> 5;
    const int wm = (w >> 1) * 32, wn = (w & 1) * 32;
    const int m0 = blockIdx.y * 128, n0 = blockIdx.x * 64;
    const int g = lane >> 2, q = lane & 3;
    const int arow = tid >> 1, ac0 = (tid & 1) * 2;
    const int brow = tid >> 2, bc0 = tid & 3;
    const uint4 z4 = make_uint4(0, 0, 0, 0);

    const uint32_t baseA = (uint32_t)__cvta_generic_to_shared(sA);
    const uint32_t baseB = (uint32_t)__cvta_generic_to_shared(sB);
    const int rA = wm + (lane & 7) + ((lane >> 3) & 1) * 8;
    const uint32_t offA0 = baseA + (uint32_t)(rA * 40 + (lane >> 4) * 8) * 2;
    const int rB = wn + (lane & 7);
    const uint32_t offB0 = baseB + (uint32_t)(rB * 40 + (lane >> 3) * 8) * 2;

    float acc[2][4][4];
#pragma unroll
    for (int i = 0; i < 2; i++)
#pragma unroll
        for (int j = 0; j < 4; j++)
#pragma unroll
            for (int u = 0; u < 4; u++) acc[i][j][u] = 0.f;

    uint4 pa[2], pb;
    auto load_regs = [&](int k0) {
#pragma unroll
        for (int e = 0; e < 2; e++)
            pa[e] = *reinterpret_cast<const uint4*>(A + (size_t)(m0 + arow) * lda + k0 + (ac0 + e) * 8);
        pb = (n0 + brow < N)
            ? *reinterpret_cast<const uint4*>(W + (size_t)(n0 + brow) * ldw + k0 + bc0 * 8)
            : z4;
    };
    auto store_smem = [&]() {
#pragma unroll
        for (int e = 0; e < 2; e++)
            *reinterpret_cast<uint4*>(&sA[arow * 40 + (ac0 + e) * 8]) = pa[e];
        *reinterpret_cast<uint4*>(&sB[brow * 40 + bc0 * 8]) = pb;
    };

    load_regs(0);
    store_smem();

    for (int k0 = 0; k0 < K; k0 += 32) {
        __syncthreads();
        const bool more = (k0 + 32) < K;
        if (more) load_regs(k0 + 32);

        uint4 bfr[4];
#pragma unroll
        for (int j = 0; j < 4; j++) bfr[j] = ldsm4(offB0 + j * 640);
#pragma unroll
        for (int kt = 0; kt < 2; kt++) {
            uint4 af0 = ldsm4(offA0 + kt * 32);
            uint4 af1 = ldsm4(offA0 + 1280 + kt * 32);
#pragma unroll
            for (int j = 0; j < 4; j++) {
                const uint32_t b0 = kt ? bfr[j].z : bfr[j].x;
                const uint32_t b1 = kt ? bfr[j].w : bfr[j].y;
                mma16(acc[0][j], af0, b0, b1);
                mma16(acc[1][j], af1, b0, b1);
            }
        }
        if (more) {
            __syncthreads();
            store_smem();
        }
    }

#pragma unroll
    for (int i = 0; i < 2; i++) {
        const int r0 = m0 + wm + i * 16 + g;
        const long long orow0 = REMAP ? (long long)((r0 & 127) * TT + (r0 >> 7)) : (long long)r0;
        const long long orow1 = REMAP ? (long long)(((r0 + 8) & 127) * TT + ((r0 + 8) >> 7)) : (long long)(r0 + 8);
#pragma unroll
        for (int j = 0; j < 4; j++) {
            const int col = n0 + wn + j * 8 + q * 2;
            float b0v = 0.f, b1v = 0.f;
            if (bias) {
                if (col < N)     b0v = bias[col];
                if (col + 1 < N) b1v = bias[col + 1];
            }
            float v00 = acc[i][j][0] + b0v, v01 = acc[i][j][1] + b1v;
            float v10 = acc[i][j][2] + b0v, v11 = acc[i][j][3] + b1v;
            if (ACT == 1) {
                v00 = fmaxf(v00, 0.f); v01 = fmaxf(v01, 0.f);
                v10 = fmaxf(v10, 0.f); v11 = fmaxf(v11, 0.f);
            } else if (ACT == 2) {
                v00 = tanhf(v00); v01 = tanhf(v01);
                v10 = tanhf(v10); v11 = tanhf(v11);
            }
            if (col < N) {
                if (OUT == 0) { C[orow0 * ldc + col] = v00; C[orow1 * ldc + col] = v10; }
                else { Cb[orow0 * ldc + col] = __float2bfloat16(v00);
                       Cb[orow1 * ldc + col] = __float2bfloat16(v10); }
            }
            if (col + 1 < N) {
                if (OUT == 0) { C[orow0 * ldc + col + 1] = v01; C[orow1 * ldc + col + 1] = v11; }
                else { Cb[orow0 * ldc + col + 1] = __float2bfloat16(v01);
                       Cb[orow1 * ldc + col + 1] = __float2bfloat16(v11); }
            }
        }
    }
}

template <int ACT, int OUT, int REMAP>
__global__ __launch_bounds__(256) void gemm2(
    const bf16* __restrict__ A, int lda,
    const bf16* __restrict__ W, int ldw,
    const float* __restrict__ bias,
    float* __restrict__ C, bf16* __restrict__ Cb, long long ldc, int N, int K)
{
    gemm2_body<ACT, OUT, REMAP>(A, lda, W, ldw, bias, C, Cb, ldc, N, K);
}

// ============ 128x128 bf16 GEMM body (256 threads, 8 warps 4x2) ============
template <int ACT, int OUT, int REMAP>
__device__ __forceinline__ void gemm3_body(
    const bf16* __restrict__ A, int lda,
    const bf16* __restrict__ W, int ldw,
    const float* __restrict__ bias,
    float* __restrict__ C, bf16* __restrict__ Cb,
    long long ldc, int N, int K)
{
    __shared__ __align__(16) bf16 sA[128 * 40];
    __shared__ __align__(16) bf16 sB[128 * 40];

    const int tid = threadIdx.x;
    const int lane = tid & 31, w = tid >> 5;
    const int wm = (w >> 1) * 32, wn = (w & 1) * 64;
    const int m0 = blockIdx.y * 128, n0 = blockIdx.x * 128;
    const int g = lane >> 2, q = lane & 3;
    const int arow = tid >> 1, ac0 = (tid & 1) * 2;
    const uint4 z4 = make_uint4(0, 0, 0, 0);

    const uint32_t baseA = (uint32_t)__cvta_generic_to_shared(sA);
    const uint32_t baseB = (uint32_t)__cvta_generic_to_shared(sB);
    const int rA = wm + (lane & 7) + ((lane >> 3) & 1) * 8;
    const uint32_t offA0 = baseA + (uint32_t)(rA * 40 + (lane >> 4) * 8) * 2;
    const int rB = wn + (lane & 7);
    const uint32_t offB0 = baseB + (uint32_t)(rB * 40 + (lane >> 3) * 8) * 2;

    float acc[2][8][4];
#pragma unroll
    for (int i = 0; i < 2; i++)
#pragma unroll
        for (int j = 0; j < 8; j++)
#pragma unroll
            for (int u = 0; u < 4; u++) acc[i][j][u] = 0.f;

    uint4 pa[2], pb[2];
    auto load_regs = [&](int k0) {
#pragma unroll
        for (int e = 0; e < 2; e++) {
            pa[e] = *reinterpret_cast<const uint4*>(A + (size_t)(m0 + arow) * lda + k0 + (ac0 + e) * 8);
            pb[e] = (n0 + arow < N)
                ? *reinterpret_cast<const uint4*>(W + (size_t)(n0 + arow) * ldw + k0 + (ac0 + e) * 8)
                : z4;
        }
    };
    auto store_smem = [&]() {
#pragma unroll
        for (int e = 0; e < 2; e++) {
            *reinterpret_cast<uint4*>(&sA[arow * 40 + (ac0 + e) * 8]) = pa[e];
            *reinterpret_cast<uint4*>(&sB[arow * 40 + (ac0 + e) * 8]) = pb[e];
        }
    };

    load_regs(0);
    store_smem();

    for (int k0 = 0; k0 < K; k0 += 32) {
        __syncthreads();
        const bool more = (k0 + 32) < K;
        if (more) load_regs(k0 + 32);

        uint4 bfr[8];
#pragma unroll
        for (int j = 0; j < 8; j++) bfr[j] = ldsm4(offB0 + j * 640);
#pragma unroll
        for (int kt = 0; kt < 2; kt++) {
            uint4 af0 = ldsm4(offA0 + kt * 32);
            uint4 af1 = ldsm4(offA0 + 1280 + kt * 32);
#pragma unroll
            for (int j = 0; j < 8; j++) {
                const uint32_t b0 = kt ? bfr[j].z : bfr[j].x;
                const uint32_t b1 = kt ? bfr[j].w : bfr[j].y;
                mma16(acc[0][j], af0, b0, b1);
                mma16(acc[1][j], af1, b0, b1);
            }
        }
        if (more) {
            __syncthreads();
            store_smem();
        }
    }

#pragma unroll
    for (int i = 0; i < 2; i++) {
        const int r0 = m0 + wm + i * 16 + g;
        const long long orow0 = REMAP ? (long long)((r0 & 127) * TT + (r0 >> 7)) : (long long)r0;
        const long long orow1 = REMAP ? (long long)(((r0 + 8) & 127) * TT + ((r0 + 8) >> 7)) : (long long)(r0 + 8);
#pragma unroll
        for (int j = 0; j < 8; j++) {
            const int col = n0 + wn + j * 8 + q * 2;
            float b0v = 0.f, b1v = 0.f;
            if (bias) {
                if (col < N)     b0v = bias[col];
                if (col + 1 < N) b1v = bias[col + 1];
            }
            float v00 = acc[i][j][0] + b0v, v01 = acc[i][j][1] + b1v;
            float v10 = acc[i][j][2] + b0v, v11 = acc[i][j][3] + b1v;
            if (ACT == 1) {
                v00 = fmaxf(v00, 0.f); v01 = fmaxf(v01, 0.f);
                v10 = fmaxf(v10, 0.f); v11 = fmaxf(v11, 0.f);
            } else if (ACT == 2) {
                v00 = tanhf(v00); v01 = tanhf(v01);
                v10 = tanhf(v10); v11 = tanhf(v11);
            }
            if (col < N) {
                if (OUT == 0) { C[orow0 * ldc + col] = v00; C[orow1 * ldc + col] = v10; }
                else { Cb[orow0 * ldc + col] = __float2bfloat16(v00);
                       Cb[orow1 * ldc + col] = __float2bfloat16(v10); }
            }
            if (col + 1 < N) {
                if (OUT == 0) { C[orow0 * ldc + col + 1] = v01; C[orow1 * ldc + col + 1] = v11; }
                else { Cb[orow0 * ldc + col + 1] = __float2bfloat16(v01);
                       Cb[orow1 * ldc + col + 1] = __float2bfloat16(v11); }
            }
        }
    }
}

template <int ACT, int OUT, int REMAP>
__global__ __launch_bounds__(256) void gemm3(
    const bf16* __restrict__ A, int lda,
    const bf16* __restrict__ W, int ldw,
    const float* __restrict__ bias,
    float* __restrict__ C, bf16* __restrict__ Cb, long long ldc, int N, int K)
{
    gemm3_body<ACT, OUT, REMAP>(A, lda, W, ldw, bias, C, Cb, ldc, N, K);
}

__global__ __launch_bounds__(256) void hs_batched(const float* __restrict__ bc)
{
    if (blockIdx.z == 0)
        gemm3_body<1, 2, 0>(g_hall + BB * DD, DD, g_WHb, DD, nullptr, nullptr, g_Hallb, DD, DD, DD);
    else
        gemm3_body<1, 2, 0>(g_uall, DD, g_Wcb, DD, bc, nullptr, g_sallb, DD, DD, DD);
}

__global__ __launch_bounds__(256) void ghsw_batched()
{
    if (blockIdx.z == 0)
        gemm2_body<0, 0, 0>(g_Hallb, DD, g_Wgb, DD, nullptr, g_gHall, nullptr, NN, NN, DD);
    else
        gemm2_body<0, 0, 0>(g_sallb, DD, g_Wsmb, DD, nullptr, g_sWsall, nullptr, NN, NN, DD);
}

// ---------------- conversion / setup kernels ----------------
__global__ void cvt_bf16_kernel(const float* __restrict__ in, bf16* __restrict__ out, int n4)
{
    int idx = blockIdx.x * blockDim.x + threadIdx.x;
    if (idx >= n4) return;
    float4 v = reinterpret_cast<const float4*>(in)[idx];
    reinterpret_cast<__nv_bfloat162*>(out)[idx * 2]     = __floats2bfloat162_rn(v.x, v.y);
    reinterpret_cast<__nv_bfloat162*>(out)[idx * 2 + 1] = __floats2bfloat162_rn(v.z, v.w);
}

__global__ void mean_kernel(const float* __restrict__ img)
{
    int idx = blockIdx.x * blockDim.x + threadIdx.x;
    if (idx >= BB * CC) return;
    int b = idx / CC, c = idx % CC;
    const float* p = img + (size_t)b * NN * CC + c;
    float s = 0.f;
#pragma unroll 7
    for (int n = 0; n < NN; n++) s += p[(size_t)n * CC];
    g_meanb[idx] = __float2bfloat16(s * (1.0f / NN));
}

__global__ void build_wbhm_kernel(const float* __restrict__ Wb, const float* __restrict__ Whi,
                                  const float* __restrict__ Wmi,
                                  const float* __restrict__ bb, const float* __restrict__ bhi,
                                  const float* __restrict__ bmi)
{
    int idx = blockIdx.x * blockDim.x + threadIdx.x;
    if (idx >= 1536 * CC) return;
    int r = idx / CC, c = idx % CC;
    float v;
    if (r < 512)       v = Wb[(size_t)r * CC + c];
    else if (r < 1024) v = Whi[(size_t)(r - 512) * CC + c];
    else               v = Wmi[(size_t)(r - 1024) * CC + c];
    g_Wbhmb[idx] = __float2bfloat16(v);
    if (c == 0) g_bbhm[r] = (r < 512) ? bb[r] : (r < 1024 ? bhi[r - 512] : bmi[r - 1024]);
}

__global__ void build_wxcat_kernel(const float* __restrict__ Wih, const float* __restrict__ Wx,
                                   const float* __restrict__ bih, const float* __restrict__ bhh)
{
    int idx = blockIdx.x * blockDim.x + threadIdx.x;
    if (idx >= GDIM * XD1) return;
    int r = idx / XD1, c = idx % XD1;
    float v = (r < 2048) ? Wih[(size_t)r * XD1 + c] : Wx[(size_t)(r - 2048) * XD1 + c];
    g_Wxcatb[idx] = __float2bfloat16(v);
    if (c == 0) g_bcat[r] = (r < 2048) ? (bih[r] + bhh[r]) : 0.f;
}

__global__ void build_whhcat_kernel(const float* __restrict__ Whh, const float* __restrict__ Wh2)
{
    int idx = blockIdx.x * blockDim.x + threadIdx.x;
    if (idx >= GDIM * DD) return;
    int r = idx / DD, c = idx % DD;
    float v = (r < 2048) ? Whh[(size_t)r * DD + c] : Wh2[(size_t)(r - 2048) * DD + c];
    g_Whhcatb[idx] = __float2bfloat16(v);
}

__global__ void hm_init_kernel()
{
    int idx = blockIdx.x * blockDim.x + threadIdx.x;
    if (idx >= BB * DD) return;
    int b = idx >> 9, d = idx & 511;
    g_hall[idx] = __float2bfloat16(g_vghm[b * 1536 + 512 + d]);
    g_m[0][idx] = g_vghm[b * 1536 + 1024 + d];
}

__global__ void xall_init_kernel(const float* __restrict__ emb, const int* __restrict__ target)
{
    int idx = blockIdx.x * blockDim.x + threadIdx.x;
    if (idx >= MT * XD1) return;
    int j = idx % XD1;
    int tb = idx / XD1;
    int b = tb % BB;
    int t = tb / BB;
    float v;
    if (j < 512) v = g_vghm[b * 1536 + j];
    else if (t == 0) v = 0.f;
    else {
        int tok = target[b * TT + t - 1];
        v = emb[(size_t)tok * EE + (j - 512)];
    }
    g_xallb[((size_t)t * BB + b) * XD1 + j] = __float2bfloat16(v);
}

// LSTM: reduce SKR preact partials + xpre, apply nonlinearity
__global__ void lstm_elem_kernel(int t)
{
    int idx = blockIdx.x * blockDim.x + threadIdx.x;
    if (idx >= BB * DD) return;
    int b = idx >> 9, d = idx & 511;
    int cur = t & 1, nxt = cur ^ 1;
    const float* ci = g_xpre + (size_t)t * BB * GDIM + (size_t)b * GDIM;
    float gi = ci[d], gf = ci[512 + d], gg = ci[1024 + d], go = ci[1536 + d], gl = ci[2048 + d];
#pragma unroll
    for (int z = 0; z < SKR; z++) {
        const float* p = g_pre_part[z] + (size_t)b * GDIM;
        gi += p[d]; gf += p[512 + d]; gg += p[1024 + d]; go += p[1536 + d]; gl += p[2048 + d];
    }
    float m2 = sigf(gf) * g_m[cur][idx] + sigf(gi) * tanhf(gg);
    float tm2 = tanhf(m2);
    g_m[nxt][idx] = m2;
    g_hall[(size_t)(t + 1) * BB * DD + idx] = __float2bfloat16(sigf(go) * tm2);
    g_uall[(size_t)t * BB * DD + idx] = __float2bfloat16(sigf(gl) * tm2);
}

// batched attention
__global__ void attn_fused_kernel(const float* __restrict__ wh, float* __restrict__ attn_out)
{
    const int r = blockIdx.x;            // t*128 + b
    const int t = r >> 7, b = r & 127;
    __shared__ float gHs[49], sWss[49], zsh[50], wsh[49];
    int tid = threadIdx.x;  // 128

    if (tid < 49) {
        gHs[tid] = g_gHall[r * 49 + tid];
        sWss[tid] = g_sWsall[r * 49 + tid];
        wsh[tid] = wh[tid];
    }
    __syncthreads();

    if (tid < 49) {
        const float* zb = g_zbase + ((size_t)b * 49 + tid) * 49;
        float acc = 0.f;
#pragma unroll 7
        for (int k = 0; k < 49; k++) acc += tanhf(zb[k] + gHs[k]) * wsh[k];
        zsh[tid] = acc;
    } else if (tid == 49) {
        float acc = 0.f;
#pragma unroll 7
        for (int k = 0; k < 49; k++) acc += tanhf(sWss[k] + gHs[k]) * wsh[k];
        zsh[49] = acc;
    }
    __syncthreads();

    if (tid == 0) {
        float mx = -1e30f;
        for (int i = 0; i < 50; i++) mx = fmaxf(mx, zsh[i]);
        float sum = 0.f;
        for (int i = 0; i < 50; i++) { zsh[i] = expf(zsh[i] - mx); sum += zsh[i]; }
        float inv = 1.f / sum;
        for (int i = 0; i < 50; i++) zsh[i] *= inv;
    }
    __syncthreads();

    if (tid < 49) attn_out[((size_t)b * TT + t) * 49 + tid] = zsh[tid];

    const float a50 = zsh[49];
    const bf16* srow = g_sallb + (size_t)r * 512;
    const bf16* Hrow = g_Hallb + (size_t)r * 512;
#pragma unroll
    for (int e = 0; e < 4; e++) {
        int d = tid + e * 128;
        float acc = a50 * __bfloat162float(srow[d]);
#pragma unroll 7
        for (int n = 0; n < 49; n++)
            acc = fmaf(zsh[n], __bfloat162float(g_Vfb[((size_t)b * 49 + n) * 512 + d]), acc);
        g_t1all[(size_t)r * 512 + d] = __float2bfloat16(__bfloat162float(Hrow[d]) + acc);
    }
}

// online single-pass max+sum log-softmax, float4
__global__ void log_softmax_kernel(float* __restrict__ logits)
{
    const int row = blockIdx.x;
    float4* x4 = reinterpret_cast<float4*>(logits + (size_t)row * VV);
    const int tid = threadIdx.x;  // 256
    float mx = -1e30f, sm = 0.f;
    for (int i = tid; i < VV / 4; i += 256) {
        float4 v = x4[i];
        float m2 = fmaxf(fmaxf(v.x, v.y), fmaxf(v.z, v.w));
        if (m2 > mx) { sm *= expf(mx - m2); mx = m2; }
        sm += expf(v.x - mx) + expf(v.y - mx) + expf(v.z - mx) + expf(v.w - mx);
    }
    __shared__ float smx[256], ssm[256];
    smx[tid] = mx; ssm[tid] = sm;
    __syncthreads();
    for (int s = 128; s; s >>= 1) {
        if (tid < s) {
            float m2 = fmaxf(smx[tid], smx[tid + s]);
            ssm[tid] = ssm[tid] * expf(smx[tid] - m2) + ssm[tid + s] * expf(smx[tid + s] - m2);
            smx[tid] = m2;
        }
        __syncthreads();
    }
    const float lse = smx[0] + logf(ssm[0]);
    for (int i = tid; i < VV / 4; i += 256) {
        float4 v = x4[i];
        v.x -= lse; v.y -= lse; v.z -= lse; v.w -= lse;
        x4[i] = v;
    }
}

// ---------------- host ----------------
static inline dim3 t2grid(int M, int N) { return dim3((N + 63) / 64, M / 128); }
static inline dim3 t3grid(int M, int N) { return dim3((N + 127) / 128, M / 128); }

extern "C" void kernel_launch(void* const* d_in, const int* in_sizes, int n_in,
                              void* d_out, int out_size)
{
    const float* img    = (const float*)d_in[0];
    const int*   target = (const int*)d_in[1];
    const float* emb    = (const float*)d_in[2];
    const float* Wa  = (const float*)d_in[3];  const float* ba  = (const float*)d_in[4];
    const float* Wb  = (const float*)d_in[5];  const float* bb  = (const float*)d_in[6];
    const float* Whi = (const float*)d_in[7];  const float* bhi = (const float*)d_in[8];
    const float* Wmi = (const float*)d_in[9];  const float* bmi = (const float*)d_in[10];
    const float* Wih = (const float*)d_in[11]; const float* bih = (const float*)d_in[12];
    const float* Whh = (const float*)d_in[13]; const float* bhh = (const float*)d_in[14];
    const float* Wv  = (const float*)d_in[15];
    const float* Wg  = (const float*)d_in[16];
    const float* wh  = (const float*)d_in[17];
    const float* WH  = (const float*)d_in[18];
    const float* Wx  = (const float*)d_in[19];
    const float* Wh2 = (const float*)d_in[20];
    const float* Wsm = (const float*)d_in[21];
    const float* Wc  = (const float*)d_in[22]; const float* bc  = (const float*)d_in[23];
    const float* Wfc = (const float*)d_in[24]; const float* bfc = (const float*)d_in[25];
    const float* Wp  = (const float*)d_in[26]; const float* bp  = (const float*)d_in[27];

    float* out_logits = (float*)d_out;                               // [B,T,VOC]
    float* out_attn   = (float*)d_out + (size_t)BB * TT * VV;        // [B,T,N]

    bf16 *p_imgb, *p_meanb, *p_Wbhmb, *p_Wab, *p_Wvb, *p_Wgb, *p_Wsmb, *p_Vfb, *p_xallb;
    bf16 *p_Wxcatb, *p_WHb, *p_Wcb, *p_Wfcb, *p_Wpb, *p_hall, *p_t1all, *p_o512all;
    float *p_vghm, *p_zbase, *p_bbhm, *p_bcat, *p_xpre;
    cudaGetSymbolAddress((void**)&p_imgb,   g_imgb);
    cudaGetSymbolAddress((void**)&p_meanb,  g_meanb);
    cudaGetSymbolAddress((void**)&p_Wbhmb,  g_Wbhmb);
    cudaGetSymbolAddress((void**)&p_Wab,    g_Wab);
    cudaGetSymbolAddress((void**)&p_Wvb,    g_Wvb);
    cudaGetSymbolAddress((void**)&p_Wgb,    g_Wgb);
    cudaGetSymbolAddress((void**)&p_Wsmb,   g_Wsmb);
    cudaGetSymbolAddress((void**)&p_Vfb,    g_Vfb);
    cudaGetSymbolAddress((void**)&p_xallb,  g_xallb);
    cudaGetSymbolAddress((void**)&p_Wxcatb, g_Wxcatb);
    cudaGetSymbolAddress((void**)&p_WHb,    g_WHb);
    cudaGetSymbolAddress((void**)&p_Wcb,    g_Wcb);
    cudaGetSymbolAddress((void**)&p_Wfcb,   g_Wfcb);
    cudaGetSymbolAddress((void**)&p_Wpb,    g_Wpb);
    cudaGetSymbolAddress((void**)&p_hall,   g_hall);
    cudaGetSymbolAddress((void**)&p_t1all,  g_t1all);
    cudaGetSymbolAddress((void**)&p_o512all,g_o512all);
    cudaGetSymbolAddress((void**)&p_vghm,   g_vghm);
    cudaGetSymbolAddress((void**)&p_zbase,  g_zbase);
    cudaGetSymbolAddress((void**)&p_bbhm,   g_bbhm);
    cudaGetSymbolAddress((void**)&p_bcat,   g_bcat);
    cudaGetSymbolAddress((void**)&p_xpre,   g_xpre);

    // one-time side stream + fork/join events (host resources; no device alloc)
    static cudaStream_t s2 = nullptr;
    static cudaEvent_t evFork = nullptr, evJoin = nullptr;
    if (!s2) {
        cudaStreamCreateWithFlags(&s2, cudaStreamNonBlocking);
        cudaEventCreateWithFlags(&evFork, cudaEventDisableTiming);
        cudaEventCreateWithFlags(&evJoin, cudaEventDisableTiming);
    }

    auto cvt = [&](cudaStream_t st, const float* in, bf16* out, int n) {
        cvt_bf16_kernel<<<(n / 4 + 255) / 256, 256, 0, st>>>(in, out, n / 4);
    };

    // ---- fork side stream ----
    cudaEventRecord(evFork, 0);
    cudaStreamWaitEvent(s2, evFork, 0);

    // ---- side stream: everything not needed until the tail ----
    cvt(s2, img, p_imgb, BB * NN * CC);
    cvt(s2, Wa,  p_Wab,  DD * CC);
    cvt(s2, Wv,  p_Wvb,  NN * DD);
    cvt(s2, Wg,  p_Wgb,  NN * DD);
    cvt(s2, Wsm, p_Wsmb, NN * DD);
    cvt(s2, WH,  p_WHb,  DD * DD);
    cvt(s2, Wc,  p_Wcb,  DD * DD);
    cvt(s2, Wfc, p_Wfcb, DD * DD);
    cvt(s2, Wp,  p_Wpb,  VV * DD);
    // Vf = relu(imgb @ Wa^T + ba)  (bf16)
    gemm2<1, 2, 0><<<t2grid(BB * NN, DD), 256, 0, s2>>>(p_imgb, CC, p_Wab, CC, ba,
                                                        nullptr, p_Vfb, DD, DD, CC);
    // zbase = Vfb @ Wv^T  (fp32)
    gemm2<0, 0, 0><<<t2grid(BB * NN, NN), 256, 0, s2>>>(p_Vfb, DD, p_Wvb, DD, nullptr,
                                                        p_zbase, nullptr, NN, NN, DD);
    cudaEventRecord(evJoin, s2);

    // ---- main stream: critical chain to the recurrence ----
    mean_kernel<<<(BB * CC + 255) / 256, 256>>>(img);
    build_wbhm_kernel<<<(1536 * CC + 255) / 256, 256>>>(Wb, Whi, Wmi, bb, bhi, bmi);
    build_wxcat_kernel<<<(GDIM * XD1 + 255) / 256, 256>>>(Wih, Wx, bih, bhh);
    build_whhcat_kernel<<<(GDIM * DD + 255) / 256, 256>>>(Whh, Wh2);
    // [vg|h0|m0] = relu(mean @ Wbhm^T + bbhm)
    gemm2<1, 0, 0><<<t2grid(BB, 1536), 256>>>(p_meanb, CC, p_Wbhmb, CC, p_bbhm,
                                              p_vghm, nullptr, 1536, 1536, CC);
    hm_init_kernel<<<(BB * DD + 255) / 256, 256>>>();
    xall_init_kernel<<<(MT * XD1 + 255) / 256, 256>>>(emb, target);
    // xpre = xall @ Wxcat^T + bcat  (all timesteps)
    gemm2<0, 0, 0><<<t2grid(MT, GDIM), 256>>>(p_xallb, XD1, p_Wxcatb, XD1, p_bcat,
                                              p_xpre, nullptr, GDIM, GDIM, XD1);

    // serial recurrence: split-K preact (320 blocks) + lstm reduce
    for (int t = 0; t < TT; t++) {
        gemm_preact_sk<<<dim3(GDIM / 64, 2, SKR), 128>>>(p_hall + (size_t)t * BB * DD);
        lstm_elem_kernel<<<(BB * DD + 255) / 256, 256>>>(t);
    }

    // ---- join: tail needs side-stream outputs (Vfb, zbase, weight cvts) ----
    cudaStreamWaitEvent(0, evJoin, 0);

    hs_batched<<<dim3(4, MT / 128, 2), 256>>>(bc);
    ghsw_batched<<<dim3(1, MT / 128, 2), 256>>>();
    attn_fused_kernel<<<MT, 128>>>(wh, out_attn);
    gemm3<2, 2, 0><<<t3grid(MT, DD), 256>>>(p_t1all, DD, p_Wfcb, DD, bfc,
                                            nullptr, p_o512all, DD, DD, DD);
    gemm3<0, 0, 1><<<t3grid(MT, VV), 256>>>(p_o512all, DD, p_Wpb, DD, bp,
                                            out_logits, nullptr, VV, VV, DD);
    log_softmax_kernel<<<MT, 256>>>(out_logits);
}